// round 15
// baseline (speedup 1.0000x reference)
#include <cuda_runtime.h>
#include <cuda_fp16.h>
#include <math.h>

#define E_   64
#define KTOP 4
#define H_   2048
#define I_   1536
#define GS_  128
#define T_   1024
#define C_   128

#if defined(__CUDA_ARCH__) && !defined(__CUDA_ARCH_FEAT_SM103_ALL) && !defined(__CUDA_ARCH_FEAT_SM100_ALL)
#define TC_OK 0
#else
#define TC_OK 1
#endif

// ---------------------------------------------------------------------------
// common helpers
// ---------------------------------------------------------------------------
__device__ __forceinline__ unsigned smem_u32(const void* p) {
    unsigned a;
    asm("{ .reg .u64 t; cvta.to.shared.u64 t, %1; cvt.u32.u64 %0, t; }" : "=r"(a) : "l"(p));
    return a;
}
__device__ __forceinline__ unsigned h2u(__half2 h) {
    return *reinterpret_cast<unsigned*>(&h);
}
__device__ __forceinline__ unsigned swoff(int off) {
    return (unsigned)(off ^ ((off >> 3) & 0x70));
}
__device__ __forceinline__ void st_sw(char* base, int off, uint4 v) {
    *reinterpret_cast<uint4*>(base + swoff(off)) = v;
}
__device__ __forceinline__ unsigned swadr(unsigned base, int row, int col) {
    return base + swoff(row * 128 + col);
}
__device__ __forceinline__ unsigned pack_sc(float s) {
    return h2u(__float2half2_rn(s));
}

__device__ __forceinline__ void cpa16(unsigned dst, const void* src) {
    asm volatile("cp.async.ca.shared.global [%0], [%1], 16;" :: "r"(dst), "l"(src));
}
__device__ __forceinline__ void cpa8(unsigned dst, const void* src) {
    asm volatile("cp.async.ca.shared.global [%0], [%1], 8;" :: "r"(dst), "l"(src));
}
#define CP_COMMIT() asm volatile("cp.async.commit_group;" ::: "memory")
#define CP_WAIT(n)  asm volatile("cp.async.wait_group %0;" :: "n"(n) : "memory")

// FP4 E2M1 x8 -> 8 fp16 via PRMT tables; sc2 = half2(scale, scale)
__device__ __forceinline__ uint4 dec8p(unsigned w, unsigned sc2) {
    const unsigned tLo = 0x3E3C3800u, tHi = 0x46444240u;
    unsigned m0, m1;
    asm("prmt.b32 %0,%1,%2,%3;" : "=r"(m0) : "r"(tLo), "r"(tHi), "r"(w & 0x7777u));
    asm("prmt.b32 %0,%1,%2,%3;" : "=r"(m1) : "r"(tLo), "r"(tHi), "r"((w >> 16) & 0x7777u));
    unsigned q4 = (w << 4) & 0x80808080u;
    unsigned q0 = w & 0x80808080u;
    unsigned r[4];
    #pragma unroll
    for (int p = 0; p < 4; p++) {
        unsigned mag  = (p < 2) ? m0 : m1;
        unsigned mctl = (p & 1) ? 0x3424u : 0x1404u;
        unsigned me, se;
        asm("prmt.b32 %0,%1,%2,%3;" : "=r"(me) : "r"(mag), "r"(0u), "r"(mctl));
        unsigned sctl = 0x4000u + (unsigned)p * 0x1010u;
        asm("prmt.b32 %0,%1,%2,%3;" : "=r"(se) : "r"(q4), "r"(q0), "r"(sctl));
        unsigned v = me | (se & 0x80008000u);
        asm("mul.rn.f16x2 %0,%1,%2;" : "=r"(r[p]) : "r"(v), "r"(sc2));
    }
    return make_uint4(r[0], r[1], r[2], r[3]);
}

// fallback-path helpers (256-thread mappings)
__device__ __forceinline__ void stage_B4(char* Bt, int4 w, unsigned sc2, int bo) {
    st_sw(Bt, bo + 0,  dec8p((unsigned)w.x, sc2));
    st_sw(Bt, bo + 16, dec8p((unsigned)w.y, sc2));
    st_sw(Bt, bo + 32, dec8p((unsigned)w.z, sc2));
    st_sw(Bt, bo + 48, dec8p((unsigned)w.w, sc2));
}
__device__ __forceinline__ void stage_A_f16(char* At, const __half* arow, int kk,
                                            int bo, int lh) {
    #pragma unroll
    for (int q = 0; q < 4; q++) {
        uint4 v = *reinterpret_cast<const uint4*>(arow + kk + lh * 32 + q * 8);
        st_sw(At, bo + q * 16, v);
    }
}

// ---------------------------------------------------------------------------
// scratch
// ---------------------------------------------------------------------------
__device__ int    g_ti[T_ * KTOP];
__device__ float  g_tw[T_ * KTOP];
__device__ int    g_cnt[E_];
__device__ int    g_slotTok[E_ * C_];
__device__ float  g_slotW[E_ * C_];
__device__ __half g_hbuf[(size_t)E_ * C_ * I_];
__device__ __half g_hsh[(size_t)T_ * I_];
__device__ __half g_xh[(size_t)T_ * H_];

// ---------------------------------------------------------------------------
// routing + dispatch + fused xcvt/zero
// ---------------------------------------------------------------------------
__global__ void routing_kernel(const float* __restrict__ x,
                               const float* __restrict__ gw) {
    __shared__ float lg[8][E_];
    int tid  = threadIdx.x;
    int tok0 = blockIdx.x * 8;
    #pragma unroll
    for (int p = 0; p < 2; p++) {
        int pair = tid + p * 256;
        int tk = pair >> 6, e = pair & 63;
        const float* xr = x  + (size_t)(tok0 + tk) * H_;
        const float* wr = gw + (size_t)e * H_;
        float acc = 0.f;
        for (int h = 0; h < H_; h += 4) {
            float4 a = *(const float4*)(xr + h);
            float4 b = *(const float4*)(wr + h);
            acc += a.x * b.x + a.y * b.y + a.z * b.z + a.w * b.w;
        }
        lg[tk][e] = acc;
    }
    __syncthreads();
    if (tid < 8) {
        int t = tok0 + tid;
        unsigned long long used = 0ull;
        float v[KTOP]; int id[KTOP];
        #pragma unroll
        for (int k = 0; k < KTOP; k++) {
            float best = -INFINITY; int bi = 0;
            for (int e = 0; e < E_; e++)
                if (!((used >> e) & 1ull) && lg[tid][e] > best) { best = lg[tid][e]; bi = e; }
            v[k] = best; id[k] = bi; used |= 1ull << bi;
        }
        float mx = v[0], w[KTOP], sum = 0.f;
        #pragma unroll
        for (int k = 0; k < KTOP; k++) { w[k] = expf(v[k] - mx); sum += w[k]; }
        #pragma unroll
        for (int k = 0; k < KTOP; k++) {
            g_ti[t * KTOP + k] = id[k];
            g_tw[t * KTOP + k] = w[k] / sum;
        }
    }
}

__global__ void dispatch_kernel() {
    __shared__ int sti[T_ * KTOP];
    int tid = threadIdx.x;
    for (int i = tid; i < T_ * KTOP; i += blockDim.x) sti[i] = g_ti[i];
    __syncthreads();
    int wid = tid >> 5, lane = tid & 31;
    int e = blockIdx.x * (blockDim.x >> 5) + wid;
    if (e < E_) {
        int cnt = 0;
        for (int base = 0; base < T_ * KTOP; base += 32) {
            int a = base + lane;
            bool m = (sti[a] == e);
            unsigned msk = __ballot_sync(0xffffffffu, m);
            if (m) {
                int c = cnt + __popc(msk & ((1u << lane) - 1u));
                if (c < C_) {
                    g_slotTok[e * C_ + c] = a >> 2;
                    g_slotW[e * C_ + c]   = g_tw[a];
                }
            }
            cnt += __popc(msk);
        }
        if (lane == 0) g_cnt[e] = cnt < C_ ? cnt : C_;
    }
}

// fused: zero y and convert x -> fp16
__global__ void xcvt_zero_kernel(const float4* __restrict__ x, float4* __restrict__ y) {
    size_t i = (size_t)blockIdx.x * blockDim.x + threadIdx.x;
    y[i] = make_float4(0.f, 0.f, 0.f, 0.f);
    float4 v = x[i];
    uint2 o;
    o.x = h2u(__float22half2_rn(make_float2(v.x, v.y)));
    o.y = h2u(__float22half2_rn(make_float2(v.z, v.w)));
    reinterpret_cast<uint2*>(g_xh)[i] = o;
}

// SMEM layouts (round-11 proven; disjoint, tiles 1024-aligned)
#define G1_PG  64
#define G1_PU  8256
#define G1_A   17408
#define G1_BG  66560
#define G1_BU  115712
#define SM1    164864
#define G2_PB  64
#define G2_A   16384
#define G2_B   65536
#define SM2    114688
#define STG    16384

#if TC_OK
// ===========================================================================
// tcgen05 path (round-14 + reordered chunk: decode first, prefetch after
// arrive so the free-wait overlaps the MMA instead of gating the decode)
// ===========================================================================
#define TC_ALLOC(sm, n)  asm volatile("tcgen05.alloc.cta_group::1.sync.aligned.shared::cta.b32 [%0], %1;" :: "r"(sm), "r"(n) : "memory")
#define TC_DEALLOC(tb,n) asm volatile("tcgen05.dealloc.cta_group::1.sync.aligned.b32 %0, %1;" :: "r"(tb), "r"(n))
#define TC_RELINQ()      asm volatile("tcgen05.relinquish_alloc_permit.cta_group::1.sync.aligned;")
#define TC_COMMIT(bar)   asm volatile("tcgen05.commit.cta_group::1.mbarrier::arrive::one.shared::cluster.b64 [%0];" :: "r"(bar) : "memory")
#define TC_FENCE_AFTER()  asm volatile("tcgen05.fence::after_thread_sync;" ::: "memory")
#define TC_FENCE_BEFORE() asm volatile("tcgen05.fence::before_thread_sync;" ::: "memory")
#define TC_WAIT_LD()      asm volatile("tcgen05.wait::ld.sync.aligned;" ::: "memory")
#define FENCE_ASYNC()     asm volatile("fence.proxy.async.shared::cta;" ::: "memory")
#define MBAR_INIT(a, c)  asm volatile("mbarrier.init.shared.b64 [%0], %1;" :: "r"(a), "r"(c) : "memory")
#define MBAR_INVAL(a)    asm volatile("mbarrier.inval.shared.b64 [%0];" :: "r"(a) : "memory")
#define MBAR_ARRIVE(a)   asm volatile("mbarrier.arrive.release.cta.shared::cta.b64 _, [%0];" :: "r"(a) : "memory")

#define MBAR_WAIT(addr, par) do {                                              \
    unsigned _m = (unsigned)(addr), _p = (unsigned)(par), _d;                  \
    asm volatile("{\n\t.reg .pred p;\n\t"                                      \
        "mbarrier.try_wait.parity.acquire.cta.shared::cta.b64 p, [%1], %2;\n\t"\
        "selp.b32 %0,1,0,p;\n\t}" : "=r"(_d) : "r"(_m), "r"(_p) : "memory");   \
    if (!_d) {                                                                 \
        asm volatile("{\n\t.reg .pred P1;\n\t"                                 \
        "WL_%=:\n\t"                                                           \
        "mbarrier.try_wait.parity.acquire.cta.shared::cta.b64 P1, [%0], %1, 0x989680;\n\t" \
        "@P1 bra.uni WD_%=;\n\t"                                               \
        "bra.uni WL_%=;\n\t"                                                   \
        "WD_%=:\n\t}" :: "r"(_m), "r"(_p) : "memory");                         \
    }                                                                          \
} while (0)

#define TC_LD32(r, ta) \
    asm volatile( \
        "tcgen05.ld.sync.aligned.32x32b.x32.b32 " \
        "{%0, %1, %2, %3, %4, %5, %6, %7, " \
        " %8, %9, %10, %11, %12, %13, %14, %15, " \
        " %16, %17, %18, %19, %20, %21, %22, %23, " \
        " %24, %25, %26, %27, %28, %29, %30, %31}, [%32];" \
        : "=r"((r)[0]),  "=r"((r)[1]),  "=r"((r)[2]),  "=r"((r)[3]), \
          "=r"((r)[4]),  "=r"((r)[5]),  "=r"((r)[6]),  "=r"((r)[7]), \
          "=r"((r)[8]),  "=r"((r)[9]),  "=r"((r)[10]), "=r"((r)[11]), \
          "=r"((r)[12]), "=r"((r)[13]), "=r"((r)[14]), "=r"((r)[15]), \
          "=r"((r)[16]), "=r"((r)[17]), "=r"((r)[18]), "=r"((r)[19]), \
          "=r"((r)[20]), "=r"((r)[21]), "=r"((r)[22]), "=r"((r)[23]), \
          "=r"((r)[24]), "=r"((r)[25]), "=r"((r)[26]), "=r"((r)[27]), \
          "=r"((r)[28]), "=r"((r)[29]), "=r"((r)[30]), "=r"((r)[31]) \
        : "r"(ta))

// idesc: dtype=F32, FP16 inputs, N=128, M=128
#define IDESC_F16 ((1u << 4) | (16u << 17) | (8u << 24))

__device__ __forceinline__ void mma_f16_ss(unsigned d, unsigned long long a,
                                           unsigned long long b, unsigned en) {
    asm volatile("{\n\t.reg .pred p;\n\tsetp.ne.u32 p, %4, 0;\n\t"
        "tcgen05.mma.cta_group::1.kind::f16 [%0], %1, %2, %3, {%5,%5,%5,%5}, p;\n\t}"
        :: "r"(d), "l"(a), "l"(b), "r"(IDESC_F16), "r"(en), "r"(0u) : "memory");
}
__device__ __forceinline__ unsigned long long make_desc(unsigned addr) {
    return ((unsigned long long)2 << 61) | ((unsigned long long)1 << 46)
         | ((unsigned long long)64 << 32) | ((unsigned long long)1 << 16)
         | ((addr >> 4) & 0x3FFFu);
}

// free barriers at sb+8/16/24 (count 1, flipped by tcgen05.commit)
// ready barriers at sb+32/40/48 (count 512, staging threads only)
__global__ __launch_bounds__(544) void mma_gemm1(
    const int* __restrict__ gp, const float* __restrict__ gsc,
    const int* __restrict__ up, const float* __restrict__ usc,
    const int* __restrict__ sgp, const float* __restrict__ sgs,
    const int* __restrict__ sup, const float* __restrict__ sus) {
    constexpr int NC = H_ / 64;   // 32
    extern __shared__ char smem[];
    const int tid = threadIdx.x, wid = tid >> 5, lid = tid & 31;
    const int j0 = blockIdx.x * 128;
    const int by = blockIdx.y;
    const bool XP = by < E_;
    const int e  = XP ? by : 0;
    const int m0 = XP ? 0 : (by - E_) * 128;
    const int nrows = XP ? g_cnt[e] : 128;
    if (nrows == 0) return;

    unsigned sb = smem_u32(smem);
    if (wid == 0) TC_ALLOC(sb, 256);
    if (tid == 0) {
        MBAR_INIT(sb + 8, 1);  MBAR_INIT(sb + 16, 1); MBAR_INIT(sb + 24, 1);
        MBAR_INIT(sb + 32, 512); MBAR_INIT(sb + 40, 512); MBAR_INIT(sb + 48, 512);
    }
    __syncthreads();
    unsigned tb;
    asm("ld.shared.b32 %0, [%1];" : "=r"(tb) : "r"(sb));

    if (tid < 512) {
        // ------------------ staging threads ------------------
        const int lrow = tid >> 2, lq = tid & 3;
        const __half* arow;
        if (XP) {
            int tok = (lrow < nrows) ? g_slotTok[e * C_ + lrow] : 0;
            arow = g_xh + (size_t)tok * H_;
        } else {
            arow = g_xh + (size_t)(m0 + lrow) * H_;
        }
        const size_t wr0 = ((size_t)(XP ? e * I_ : 0) + j0 + lrow) * (H_ / 8) + lq * 2;
        const int* gpr = (XP ? gp : sgp) + wr0;
        const int* upr = (XP ? up : sup) + wr0;
        const size_t sc0 = (size_t)(XP ? e * (H_ / GS_) * I_ : 0) + j0 + lrow;
        const float* gsp = (XP ? gsc : sgs) + sc0;
        const float* usp = (XP ? usc : sus) + sc0;
        const int bo = lrow * 128 + lq * 32;
        const __half* asrc0 = arow + lq * 16;

        // prologue: G0={B(0) slot0, A(0) stage0}; G1={B(1) slot1, A(1) stage1}
        cpa8(sb + G1_PG + tid * 8, gpr);
        cpa8(sb + G1_PU + tid * 8, upr);
        cpa16(sb + G1_A + swoff(bo),      asrc0);
        cpa16(sb + G1_A + swoff(bo + 16), asrc0 + 8);
        CP_COMMIT();
        cpa8(sb + G1_PG + 4096 + tid * 8, gpr + 8);
        cpa8(sb + G1_PU + 4096 + tid * 8, upr + 8);
        cpa16(sb + G1_A + STG + swoff(bo),      asrc0 + 64);
        cpa16(sb + G1_A + STG + swoff(bo + 16), asrc0 + 72);
        CP_COMMIT();
        unsigned sg2 = pack_sc(gsp[0]), su2 = pack_sc(usp[0]);

        for (int c = 0; c < NC; c++) {
            const int st = c % 3;
            CP_WAIT(0);   // A(c), B rings all landed
            int2 wg = *(const int2*)(smem + G1_PG + (c & 1) * 4096 + tid * 8);
            int2 wu = *(const int2*)(smem + G1_PU + (c & 1) * 4096 + tid * 8);
            char* Bg = smem + G1_BG + st * STG;
            char* Bu = smem + G1_BU + st * STG;
            st_sw(Bg, bo + 0,  dec8p((unsigned)wg.x, sg2));
            st_sw(Bg, bo + 16, dec8p((unsigned)wg.y, sg2));
            st_sw(Bu, bo + 0,  dec8p((unsigned)wu.x, su2));
            st_sw(Bu, bo + 16, dec8p((unsigned)wu.y, su2));
            FENCE_ASYNC();
            MBAR_ARRIVE(sb + 32 + 8 * st);      // staging(c) done (this thread)

            // prefetch — off the critical path, overlapping MMA(c)
            if (c + 1 < NC) {
                if (c >= 1) {
                    if (c >= 2)   // stage (c+1)%3 freed by MMA(c-2)
                        MBAR_WAIT(sb + 8 + 8 * ((c - 2) % 3), ((c - 2) / 3) & 1);
                    unsigned adst = sb + G1_A + ((c + 1) % 3) * STG;
                    const __half* asrc = asrc0 + (c + 1) * 64;
                    cpa16(adst + swoff(bo),      asrc);
                    cpa16(adst + swoff(bo + 16), asrc + 8);
                }
                if (((c + 1) & 1) == 0) {
                    sg2 = pack_sc(gsp[(size_t)((c + 1) >> 1) * I_]);
                    su2 = pack_sc(usp[(size_t)((c + 1) >> 1) * I_]);
                }
            }
            if (c + 2 < NC) {
                cpa8(sb + G1_PG + (c & 1) * 4096 + tid * 8, gpr + (c + 2) * 8);
                cpa8(sb + G1_PU + (c & 1) * 4096 + tid * 8, upr + (c + 2) * 8);
            }
            CP_COMMIT();
        }
        {
            const int ls = (NC - 1) % 3;
            MBAR_WAIT(sb + 8 + 8 * ls, (((NC - 1) - ls) / 3) & 1);
        }
    } else if (tid == 512) {
        // ------------------ MMA warp (elected thread) ------------------
        for (int c = 0; c < NC; c++) {
            const int st = c % 3;
            MBAR_WAIT(sb + 32 + 8 * st, (c / 3) & 1);   // all 512 staged
            unsigned long long ad = make_desc(sb + G1_A  + st * STG);
            unsigned long long gd = make_desc(sb + G1_BG + st * STG);
            unsigned long long ud = make_desc(sb + G1_BU + st * STG);
            #pragma unroll
            for (int ks = 0; ks < 4; ks++) {
                unsigned en = (c > 0 || ks > 0) ? 1u : 0u;
                mma_f16_ss(tb,       ad + ks * 2, gd + ks * 2, en);
                mma_f16_ss(tb + 128, ad + ks * 2, ud + ks * 2, en);
            }
            TC_COMMIT(sb + 8 + 8 * st);
        }
    }
    TC_FENCE_AFTER();

    // epilogue: warps 0-15 only; warp 16 just syncs
    if (wid < 16) {
        const int r = (wid & 3) * 32 + lid;
        const int cb = (wid >> 2) * 32;
        bool valid = XP ? (r < nrows) : true;
        __half* drow = XP ? (g_hbuf + ((size_t)e * C_ + r) * I_)
                          : (g_hsh  + (size_t)(m0 + r) * I_);
        unsigned gr[32], ur[32];
        TC_LD32(gr, tb + cb);
        TC_LD32(ur, tb + 128 + cb);
        TC_WAIT_LD();
        if (valid) {
            #pragma unroll
            for (int q = 0; q < 4; q++) {
                float v[8];
                #pragma unroll
                for (int t = 0; t < 8; t++) {
                    int j = q * 8 + t;
                    float gv = __uint_as_float(gr[j]);
                    float uv = __uint_as_float(ur[j]);
                    v[t] = gv / (1.f + __expf(-gv)) * uv;
                }
                uint4 o;
                o.x = h2u(__float22half2_rn(make_float2(v[0], v[1])));
                o.y = h2u(__float22half2_rn(make_float2(v[2], v[3])));
                o.z = h2u(__float22half2_rn(make_float2(v[4], v[5])));
                o.w = h2u(__float22half2_rn(make_float2(v[6], v[7])));
                *reinterpret_cast<uint4*>(drow + j0 + cb + q * 8) = o;
            }
        }
        TC_FENCE_BEFORE();
    }
    __syncthreads();
    if (tid == 0) {
        MBAR_INVAL(sb + 8);  MBAR_INVAL(sb + 16); MBAR_INVAL(sb + 24);
        MBAR_INVAL(sb + 32); MBAR_INVAL(sb + 40); MBAR_INVAL(sb + 48);
    }
    __syncthreads();
    if (wid == 0) { TC_RELINQ(); TC_DEALLOC(tb, 256); }
}

__global__ __launch_bounds__(544) void mma_gemm2(
    const int* __restrict__ dp, const float* __restrict__ dsc,
    const int* __restrict__ sdp, const float* __restrict__ sds,
    float* __restrict__ y) {
    constexpr int NC = I_ / 64;   // 24
    extern __shared__ char smem[];
    const int tid = threadIdx.x, wid = tid >> 5, lid = tid & 31;
    const int n0 = blockIdx.x * 128;
    const int by = blockIdx.y;
    const bool XP = by < E_;
    const int e  = XP ? by : 0;
    const int m0 = XP ? 0 : (by - E_) * 128;
    const int nrows = XP ? g_cnt[e] : 128;
    if (nrows == 0) return;

    unsigned sb = smem_u32(smem);
    if (wid == 0) TC_ALLOC(sb, 128);
    if (tid == 0) {
        MBAR_INIT(sb + 8, 1);  MBAR_INIT(sb + 16, 1); MBAR_INIT(sb + 24, 1);
        MBAR_INIT(sb + 32, 512); MBAR_INIT(sb + 40, 512); MBAR_INIT(sb + 48, 512);
    }
    __syncthreads();
    unsigned tb;
    asm("ld.shared.b32 %0, [%1];" : "=r"(tb) : "r"(sb));

    if (tid < 512) {
        const int lrow = tid >> 2, lq = tid & 3;
        const __half* arow = XP ? (g_hbuf + ((size_t)e * C_ + lrow) * I_)
                                : (g_hsh  + (size_t)(m0 + lrow) * I_);
        const int* dpr = (XP ? dp : sdp)
                       + ((size_t)(XP ? e * H_ : 0) + n0 + lrow) * (I_ / 8) + lq * 2;
        const float* dsp = (XP ? dsc : sds)
                         + (size_t)(XP ? e * (I_ / GS_) * H_ : 0) + n0 + lrow;
        const int bo = lrow * 128 + lq * 32;
        const __half* asrc0 = arow + lq * 16;

        // prologue: G0={Bp(0), A(0)}; G1={Bp(1), A(1)}
        cpa8(sb + G2_PB + tid * 8, dpr);
        cpa16(sb + G2_A + swoff(bo),      asrc0);
        cpa16(sb + G2_A + swoff(bo + 16), asrc0 + 8);
        CP_COMMIT();
        cpa8(sb + G2_PB + 4096 + tid * 8, dpr + 8);
        cpa16(sb + G2_A + STG + swoff(bo),      asrc0 + 64);
        cpa16(sb + G2_A + STG + swoff(bo + 16), asrc0 + 72);
        CP_COMMIT();
        unsigned sd2 = pack_sc(dsp[0]);

        for (int c = 0; c < NC; c++) {
            const int st = c % 3;
            CP_WAIT(0);
            int2 wd = *(const int2*)(smem + G2_PB + (c & 1) * 4096 + tid * 8);
            char* Bt = smem + G2_B + st * STG;
            st_sw(Bt, bo + 0,  dec8p((unsigned)wd.x, sd2));
            st_sw(Bt, bo + 16, dec8p((unsigned)wd.y, sd2));
            FENCE_ASYNC();
            MBAR_ARRIVE(sb + 32 + 8 * st);

            if (c + 1 < NC) {
                if (c >= 1) {
                    if (c >= 2)
                        MBAR_WAIT(sb + 8 + 8 * ((c - 2) % 3), ((c - 2) / 3) & 1);
                    unsigned adst = sb + G2_A + ((c + 1) % 3) * STG;
                    const __half* asrc = asrc0 + (c + 1) * 64;
                    cpa16(adst + swoff(bo),      asrc);
                    cpa16(adst + swoff(bo + 16), asrc + 8);
                }
                if (((c + 1) & 1) == 0)
                    sd2 = pack_sc(dsp[(size_t)((c + 1) >> 1) * H_]);
            }
            if (c + 2 < NC)
                cpa8(sb + G2_PB + (c & 1) * 4096 + tid * 8, dpr + (c + 2) * 8);
            CP_COMMIT();
        }
        {
            const int ls = (NC - 1) % 3;
            MBAR_WAIT(sb + 8 + 8 * ls, (((NC - 1) - ls) / 3) & 1);
        }
    } else if (tid == 512) {
        for (int c = 0; c < NC; c++) {
            const int st = c % 3;
            MBAR_WAIT(sb + 32 + 8 * st, (c / 3) & 1);
            unsigned long long ad = make_desc(sb + G2_A + st * STG);
            unsigned long long bd = make_desc(sb + G2_B + st * STG);
            #pragma unroll
            for (int ks = 0; ks < 4; ks++) {
                unsigned en = (c > 0 || ks > 0) ? 1u : 0u;
                mma_f16_ss(tb, ad + ks * 2, bd + ks * 2, en);
            }
            TC_COMMIT(sb + 8 + 8 * st);
        }
    }
    TC_FENCE_AFTER();

    if (wid < 16) {
        const int r = (wid & 3) * 32 + lid;
        const int cb = (wid >> 2) * 32;
        bool valid = XP ? (r < nrows) : true;
        int tok = 0; float wgt = 0.f;
        if (XP) { if (valid) { tok = g_slotTok[e * C_ + r]; wgt = g_slotW[e * C_ + r]; } }
        else    { tok = m0 + r; wgt = 1.f; }
        unsigned dr[32];
        TC_LD32(dr, tb + cb);
        TC_WAIT_LD();
        if (valid) {
            float* dst = y + (size_t)tok * H_ + n0 + cb;
            #pragma unroll
            for (int j = 0; j < 32; j += 4) {
                float v0 = wgt * __uint_as_float(dr[j]);
                float v1 = wgt * __uint_as_float(dr[j + 1]);
                float v2 = wgt * __uint_as_float(dr[j + 2]);
                float v3 = wgt * __uint_as_float(dr[j + 3]);
                asm volatile("red.global.add.v4.f32 [%0], {%1,%2,%3,%4};"
                    :: "l"(dst + j), "f"(v0), "f"(v1), "f"(v2), "f"(v3) : "memory");
            }
        }
        TC_FENCE_BEFORE();
    }
    __syncthreads();
    if (tid == 0) {
        MBAR_INVAL(sb + 8);  MBAR_INVAL(sb + 16); MBAR_INVAL(sb + 24);
        MBAR_INVAL(sb + 32); MBAR_INVAL(sb + 40); MBAR_INVAL(sb + 48);
    }
    __syncthreads();
    if (wid == 0) { TC_RELINQ(); TC_DEALLOC(tb, 128); }
}

#else  // !TC_OK
// ===========================================================================
// fallback: mma.sync (compiles for plain sm_103; never selected on GB300 —
// first 256 threads do the work, syncs stay block-wide)
// ===========================================================================
__device__ __forceinline__ void ldm_x4(unsigned r[4], unsigned a) {
    asm volatile("ldmatrix.sync.aligned.m8n8.x4.shared.b16 {%0,%1,%2,%3}, [%4];"
                 : "=r"(r[0]), "=r"(r[1]), "=r"(r[2]), "=r"(r[3]) : "r"(a));
}
__device__ __forceinline__ void ldm_x2(unsigned r[2], unsigned a) {
    asm volatile("ldmatrix.sync.aligned.m8n8.x2.shared.b16 {%0,%1}, [%2];"
                 : "=r"(r[0]), "=r"(r[1]) : "r"(a));
}
__device__ __forceinline__ void mma16816(float* d, const unsigned* a, const unsigned* b) {
    asm volatile("mma.sync.aligned.m16n8k16.row.col.f32.f16.f16.f32 "
        "{%0,%1,%2,%3}, {%4,%5,%6,%7}, {%8,%9}, {%0,%1,%2,%3};"
        : "+f"(d[0]), "+f"(d[1]), "+f"(d[2]), "+f"(d[3])
        : "r"(a[0]), "r"(a[1]), "r"(a[2]), "r"(a[3]), "r"(b[0]), "r"(b[1]));
}

__global__ __launch_bounds__(544) void mma_gemm1(
    const int* __restrict__ gp, const float* __restrict__ gsc,
    const int* __restrict__ up, const float* __restrict__ usc,
    const int* __restrict__ sgp, const float* __restrict__ sgs,
    const int* __restrict__ sup, const float* __restrict__ sus) {
    constexpr int NC = H_ / 64;
    extern __shared__ char smem[];
    const int tid = threadIdx.x;
    const bool act = tid < 256;
    const int t2 = tid & 255, wid = t2 >> 5, lane = t2 & 31;
    const int j0 = blockIdx.x * 128;
    const int by = blockIdx.y;
    const bool XP = by < E_;
    const int e  = XP ? by : 0;
    const int m0 = XP ? 0 : (by - E_) * 128;
    const int nrows = XP ? g_cnt[e] : 128;
    if (nrows == 0) return;

    unsigned sb = smem_u32(smem);
    const unsigned Ab = sb + G1_A, Bgb = sb + G1_BG, Bub = sb + G1_BU;
    const int lrow = t2 >> 1, lh = t2 & 1;
    const __half* arow;
    if (XP) {
        int tok = (lrow < nrows) ? g_slotTok[e * C_ + lrow] : 0;
        arow = g_xh + (size_t)tok * H_;
    } else {
        arow = g_xh + (size_t)(m0 + lrow) * H_;
    }
    const size_t wr0 = ((size_t)(XP ? e * I_ : 0) + j0 + lrow) * (H_ / 8) + lh * 4;
    const int* gpr = (XP ? gp : sgp) + wr0;
    const int* upr = (XP ? up : sup) + wr0;
    const size_t sc0 = (size_t)(XP ? e * (H_ / GS_) * I_ : 0) + j0 + lrow;
    const float* gsp = (XP ? gsc : sgs) + sc0;
    const float* usp = (XP ? usc : sus) + sc0;
    const int bo = lrow * 128 + lh * 64;
    const int wm = wid >> 2, wn = wid & 3;

    float ag[4][4][4], au[4][4][4];
    #pragma unroll
    for (int i = 0; i < 4; i++)
        #pragma unroll
        for (int j = 0; j < 4; j++)
            #pragma unroll
            for (int q = 0; q < 4; q++) { ag[i][j][q] = 0.f; au[i][j][q] = 0.f; }

    for (int c = 0; c < NC; c++) {
        int kk = c * 64;
        if (act) {
            stage_A_f16(smem + G1_A, arow, kk, bo, lh);
            stage_B4(smem + G1_BG, *(const int4*)(gpr + (kk >> 3)),
                     pack_sc(gsp[(size_t)(kk >> 7) * I_]), bo);
            stage_B4(smem + G1_BU, *(const int4*)(upr + (kk >> 3)),
                     pack_sc(usp[(size_t)(kk >> 7) * I_]), bo);
        }
        __syncthreads();
        if (act) {
            #pragma unroll
            for (int ks = 0; ks < 4; ks++) {
                unsigned af[4][4];
                #pragma unroll
                for (int mt = 0; mt < 4; mt++)
                    ldm_x4(af[mt], swadr(Ab, wm * 64 + mt * 16 + (lane & 15),
                                         ks * 32 + (lane >> 4) * 16));
                #pragma unroll
                for (int nt = 0; nt < 4; nt++) {
                    int brow = wn * 32 + nt * 8 + (lane & 7);
                    int bcol = ks * 32 + ((lane >> 3) & 1) * 16;
                    unsigned bg[2], bu[2];
                    ldm_x2(bg, swadr(Bgb, brow, bcol));
                    ldm_x2(bu, swadr(Bub, brow, bcol));
                    #pragma unroll
                    for (int mt = 0; mt < 4; mt++) {
                        mma16816(ag[mt][nt], af[mt], bg);
                        mma16816(au[mt][nt], af[mt], bu);
                    }
                }
            }
        }
        __syncthreads();
    }
    if (act) {
        const int g = lane >> 2, cq = lane & 3;
        #pragma unroll
        for (int mt = 0; mt < 4; mt++)
            #pragma unroll
            for (int nt = 0; nt < 4; nt++) {
                int nn = j0 + wn * 32 + nt * 8 + cq * 2;
                #pragma unroll
                for (int hrow = 0; hrow < 2; hrow++) {
                    int r = wm * 64 + mt * 16 + g + hrow * 8;
                    if (XP && r >= nrows) continue;
                    float g0 = ag[mt][nt][hrow * 2], g1 = ag[mt][nt][hrow * 2 + 1];
                    float u0 = au[mt][nt][hrow * 2], u1 = au[mt][nt][hrow * 2 + 1];
                    float v0 = g0 / (1.f + expf(-g0)) * u0;
                    float v1 = g1 / (1.f + expf(-g1)) * u1;
                    __half* dst = (XP ? g_hbuf + ((size_t)e * C_ + r) * I_
                                      : g_hsh + (size_t)(m0 + r) * I_) + nn;
                    *reinterpret_cast<__half2*>(dst) =
                        __float22half2_rn(make_float2(v0, v1));
                }
            }
    }
}

__global__ __launch_bounds__(544) void mma_gemm2(
    const int* __restrict__ dp, const float* __restrict__ dsc,
    const int* __restrict__ sdp, const float* __restrict__ sds,
    float* __restrict__ y) {
    constexpr int NC = I_ / 64;
    extern __shared__ char smem[];
    const int tid = threadIdx.x;
    const bool act = tid < 256;
    const int t2 = tid & 255, wid = t2 >> 5, lane = t2 & 31;
    const int n0 = blockIdx.x * 128;
    const int by = blockIdx.y;
    const bool XP = by < E_;
    const int e  = XP ? by : 0;
    const int m0 = XP ? 0 : (by - E_) * 128;
    const int nrows = XP ? g_cnt[e] : 128;
    if (nrows == 0) return;

    unsigned sb = smem_u32(smem);
    const unsigned Ab = sb + G2_A, Bb = sb + G2_B;
    const int lrow = t2 >> 1, lh = t2 & 1;
    const __half* arow = XP ? (g_hbuf + ((size_t)e * C_ + lrow) * I_)
                            : (g_hsh  + (size_t)(m0 + lrow) * I_);
    const int* dpr = (XP ? dp : sdp)
                   + ((size_t)(XP ? e * H_ : 0) + n0 + lrow) * (I_ / 8) + lh * 4;
    const float* dsp = (XP ? dsc : sds)
                     + (size_t)(XP ? e * (I_ / GS_) * H_ : 0) + n0 + lrow;
    const int bo = lrow * 128 + lh * 64;
    const int wm = wid >> 2, wn = wid & 3;

    float acc[4][4][4];
    #pragma unroll
    for (int i = 0; i < 4; i++)
        #pragma unroll
        for (int j = 0; j < 4; j++)
            #pragma unroll
            for (int q = 0; q < 4; q++) acc[i][j][q] = 0.f;

    for (int c = 0; c < NC; c++) {
        int kk = c * 64;
        if (act) {
            stage_A_f16(smem + G2_A, arow, kk, bo, lh);
            stage_B4(smem + G2_B, *(const int4*)(dpr + (kk >> 3)),
                     pack_sc(dsp[(size_t)(kk >> 7) * H_]), bo);
        }
        __syncthreads();
        if (act) {
            #pragma unroll
            for (int ks = 0; ks < 4; ks++) {
                unsigned af[4][4];
                #pragma unroll
                for (int mt = 0; mt < 4; mt++)
                    ldm_x4(af[mt], swadr(Ab, wm * 64 + mt * 16 + (lane & 15),
                                         ks * 32 + (lane >> 4) * 16));
                #pragma unroll
                for (int nt = 0; nt < 4; nt++) {
                    int brow = wn * 32 + nt * 8 + (lane & 7);
                    int bcol = ks * 32 + ((lane >> 3) & 1) * 16;
                    unsigned bf[2];
                    ldm_x2(bf, swadr(Bb, brow, bcol));
                    #pragma unroll
                    for (int mt = 0; mt < 4; mt++)
                        mma16816(acc[mt][nt], af[mt], bf);
                }
            }
        }
        __syncthreads();
    }
    if (act) {
        const int g = lane >> 2, cq = lane & 3;
        #pragma unroll
        for (int mt = 0; mt < 4; mt++)
            #pragma unroll
            for (int hrow = 0; hrow < 2; hrow++) {
                int r = wm * 64 + mt * 16 + g + hrow * 8;
                if (XP && r >= nrows) continue;
                int tok; float wgt;
                if (XP) { tok = g_slotTok[e * C_ + r]; wgt = g_slotW[e * C_ + r]; }
                else    { tok = m0 + r; wgt = 1.f; }
                #pragma unroll
                for (int nt = 0; nt < 4; nt++) {
                    int nn = n0 + wn * 32 + nt * 8 + cq * 2;
                    float* dst = y + (size_t)tok * H_ + nn;
                    atomicAdd(dst,     wgt * acc[mt][nt][hrow * 2]);
                    atomicAdd(dst + 1, wgt * acc[mt][nt][hrow * 2 + 1]);
                }
            }
    }
}
#endif  // TC_OK

// ---------------------------------------------------------------------------
// launch
// ---------------------------------------------------------------------------
extern "C" void kernel_launch(void* const* d_in, const int* in_sizes, int n_in,
                              void* d_out, int out_size) {
    const float* x   = (const float*)d_in[0];
    const float* gw  = (const float*)d_in[1];
    const float* gsc = (const float*)d_in[2];
    const float* usc = (const float*)d_in[3];
    const float* dsc = (const float*)d_in[4];
    const float* sgs = (const float*)d_in[5];
    const float* sus = (const float*)d_in[6];
    const float* sds = (const float*)d_in[7];
    const int*   gpk = (const int*)d_in[8];
    const int*   upk = (const int*)d_in[9];
    const int*   dpk = (const int*)d_in[10];
    const int*   sgp = (const int*)d_in[11];
    const int*   sup = (const int*)d_in[12];
    const int*   sdp = (const int*)d_in[13];
    float* y = (float*)d_out;

    cudaFuncSetAttribute(mma_gemm1, cudaFuncAttributeMaxDynamicSharedMemorySize, SM1);
    cudaFuncSetAttribute(mma_gemm2, cudaFuncAttributeMaxDynamicSharedMemorySize, SM2);

    routing_kernel<<<T_ / 8, 256>>>(x, gw);
    dispatch_kernel<<<2, 1024>>>();
    xcvt_zero_kernel<<<(T_ * H_ / 4) / 512, 512>>>((const float4*)x, (float4*)y);

    // stage 1: SwiGLU intermediates (experts y=0..63, shared tiles y=64..71)
    mma_gemm1<<<dim3(I_ / 128, E_ + T_ / 128), 544, SM1>>>(
        gpk, gsc, upk, usc, sgp, sgs, sup, sus);

    // stage 2: down-proj, all paths combine into zeroed y via red.v4
    mma_gemm2<<<dim3(H_ / 128, E_ + T_ / 128), 544, SM2>>>(
        dpk, dsc, sdp, sds, y);
}

// round 16
// speedup vs baseline: 1.0612x; 1.0612x over previous
#include <cuda_runtime.h>
#include <cuda_fp16.h>
#include <math.h>

#define E_   64
#define KTOP 4
#define H_   2048
#define I_   1536
#define GS_  128
#define T_   1024
#define C_   128

#if defined(__CUDA_ARCH__) && !defined(__CUDA_ARCH_FEAT_SM103_ALL) && !defined(__CUDA_ARCH_FEAT_SM100_ALL)
#define TC_OK 0
#else
#define TC_OK 1
#endif

// ---------------------------------------------------------------------------
// common helpers
// ---------------------------------------------------------------------------
__device__ __forceinline__ unsigned smem_u32(const void* p) {
    unsigned a;
    asm("{ .reg .u64 t; cvta.to.shared.u64 t, %1; cvt.u32.u64 %0, t; }" : "=r"(a) : "l"(p));
    return a;
}
__device__ __forceinline__ unsigned h2u(__half2 h) {
    return *reinterpret_cast<unsigned*>(&h);
}
__device__ __forceinline__ unsigned swoff(int off) {
    return (unsigned)(off ^ ((off >> 3) & 0x70));
}
__device__ __forceinline__ void st_sw(char* base, int off, uint4 v) {
    *reinterpret_cast<uint4*>(base + swoff(off)) = v;
}
__device__ __forceinline__ unsigned swadr(unsigned base, int row, int col) {
    return base + swoff(row * 128 + col);
}
__device__ __forceinline__ unsigned pack_sc(float s) {
    return h2u(__float2half2_rn(s));
}

__device__ __forceinline__ void cpa16(unsigned dst, const void* src) {
    asm volatile("cp.async.ca.shared.global [%0], [%1], 16;" :: "r"(dst), "l"(src));
}
__device__ __forceinline__ void cpa8(unsigned dst, const void* src) {
    asm volatile("cp.async.ca.shared.global [%0], [%1], 8;" :: "r"(dst), "l"(src));
}
#define CP_COMMIT() asm volatile("cp.async.commit_group;" ::: "memory")
#define CP_WAIT(n)  asm volatile("cp.async.wait_group %0;" :: "n"(n) : "memory")

// FP4 E2M1 x8 -> 8 fp16 via PRMT tables; sc2 = half2(scale, scale)
__device__ __forceinline__ uint4 dec8p(unsigned w, unsigned sc2) {
    const unsigned tLo = 0x3E3C3800u, tHi = 0x46444240u;
    unsigned m0, m1;
    asm("prmt.b32 %0,%1,%2,%3;" : "=r"(m0) : "r"(tLo), "r"(tHi), "r"(w & 0x7777u));
    asm("prmt.b32 %0,%1,%2,%3;" : "=r"(m1) : "r"(tLo), "r"(tHi), "r"((w >> 16) & 0x7777u));
    unsigned q4 = (w << 4) & 0x80808080u;
    unsigned q0 = w & 0x80808080u;
    unsigned r[4];
    #pragma unroll
    for (int p = 0; p < 4; p++) {
        unsigned mag  = (p < 2) ? m0 : m1;
        unsigned mctl = (p & 1) ? 0x3424u : 0x1404u;
        unsigned me, se;
        asm("prmt.b32 %0,%1,%2,%3;" : "=r"(me) : "r"(mag), "r"(0u), "r"(mctl));
        unsigned sctl = 0x4000u + (unsigned)p * 0x1010u;
        asm("prmt.b32 %0,%1,%2,%3;" : "=r"(se) : "r"(q4), "r"(q0), "r"(sctl));
        unsigned v = me | (se & 0x80008000u);
        asm("mul.rn.f16x2 %0,%1,%2;" : "=r"(r[p]) : "r"(v), "r"(sc2));
    }
    return make_uint4(r[0], r[1], r[2], r[3]);
}

// fallback-path helpers (256-thread mappings)
__device__ __forceinline__ void stage_B4(char* Bt, int4 w, unsigned sc2, int bo) {
    st_sw(Bt, bo + 0,  dec8p((unsigned)w.x, sc2));
    st_sw(Bt, bo + 16, dec8p((unsigned)w.y, sc2));
    st_sw(Bt, bo + 32, dec8p((unsigned)w.z, sc2));
    st_sw(Bt, bo + 48, dec8p((unsigned)w.w, sc2));
}
__device__ __forceinline__ void stage_A_f16(char* At, const __half* arow, int kk,
                                            int bo, int lh) {
    #pragma unroll
    for (int q = 0; q < 4; q++) {
        uint4 v = *reinterpret_cast<const uint4*>(arow + kk + lh * 32 + q * 8);
        st_sw(At, bo + q * 16, v);
    }
}

// ---------------------------------------------------------------------------
// scratch
// ---------------------------------------------------------------------------
__device__ int    g_ti[T_ * KTOP];
__device__ float  g_tw[T_ * KTOP];
__device__ int    g_cnt[E_];
__device__ int    g_slotTok[E_ * C_];
__device__ float  g_slotW[E_ * C_];
__device__ __half g_hbuf[(size_t)E_ * C_ * I_];
__device__ __half g_hsh[(size_t)T_ * I_];
__device__ __half g_xh[(size_t)T_ * H_];

// ---------------------------------------------------------------------------
// routing + dispatch + fused xcvt/zero
// ---------------------------------------------------------------------------
__global__ void routing_kernel(const float* __restrict__ x,
                               const float* __restrict__ gw) {
    __shared__ float lg[8][E_];
    int tid  = threadIdx.x;
    int tok0 = blockIdx.x * 8;
    #pragma unroll
    for (int p = 0; p < 2; p++) {
        int pair = tid + p * 256;
        int tk = pair >> 6, e = pair & 63;
        const float* xr = x  + (size_t)(tok0 + tk) * H_;
        const float* wr = gw + (size_t)e * H_;
        float acc = 0.f;
        for (int h = 0; h < H_; h += 4) {
            float4 a = *(const float4*)(xr + h);
            float4 b = *(const float4*)(wr + h);
            acc += a.x * b.x + a.y * b.y + a.z * b.z + a.w * b.w;
        }
        lg[tk][e] = acc;
    }
    __syncthreads();
    if (tid < 8) {
        int t = tok0 + tid;
        unsigned long long used = 0ull;
        float v[KTOP]; int id[KTOP];
        #pragma unroll
        for (int k = 0; k < KTOP; k++) {
            float best = -INFINITY; int bi = 0;
            for (int e = 0; e < E_; e++)
                if (!((used >> e) & 1ull) && lg[tid][e] > best) { best = lg[tid][e]; bi = e; }
            v[k] = best; id[k] = bi; used |= 1ull << bi;
        }
        float mx = v[0], w[KTOP], sum = 0.f;
        #pragma unroll
        for (int k = 0; k < KTOP; k++) { w[k] = expf(v[k] - mx); sum += w[k]; }
        #pragma unroll
        for (int k = 0; k < KTOP; k++) {
            g_ti[t * KTOP + k] = id[k];
            g_tw[t * KTOP + k] = w[k] / sum;
        }
    }
}

__global__ void dispatch_kernel() {
    __shared__ int sti[T_ * KTOP];
    int tid = threadIdx.x;
    for (int i = tid; i < T_ * KTOP; i += blockDim.x) sti[i] = g_ti[i];
    __syncthreads();
    int wid = tid >> 5, lane = tid & 31;
    int e = blockIdx.x * (blockDim.x >> 5) + wid;
    if (e < E_) {
        int cnt = 0;
        for (int base = 0; base < T_ * KTOP; base += 32) {
            int a = base + lane;
            bool m = (sti[a] == e);
            unsigned msk = __ballot_sync(0xffffffffu, m);
            if (m) {
                int c = cnt + __popc(msk & ((1u << lane) - 1u));
                if (c < C_) {
                    g_slotTok[e * C_ + c] = a >> 2;
                    g_slotW[e * C_ + c]   = g_tw[a];
                }
            }
            cnt += __popc(msk);
        }
        if (lane == 0) g_cnt[e] = cnt < C_ ? cnt : C_;
    }
}

// fused: zero y and convert x -> fp16
__global__ void xcvt_zero_kernel(const float4* __restrict__ x, float4* __restrict__ y) {
    size_t i = (size_t)blockIdx.x * blockDim.x + threadIdx.x;
    y[i] = make_float4(0.f, 0.f, 0.f, 0.f);
    float4 v = x[i];
    uint2 o;
    o.x = h2u(__float22half2_rn(make_float2(v.x, v.y)));
    o.y = h2u(__float22half2_rn(make_float2(v.z, v.w)));
    reinterpret_cast<uint2*>(g_xh)[i] = o;
}

// SMEM layouts (round-11 proven; disjoint, tiles 1024-aligned)
#define G1_PG  64
#define G1_PU  8256
#define G1_A   17408
#define G1_BG  66560
#define G1_BU  115712
#define SM1    164864
#define G2_PB  64
#define G2_A   16384
#define G2_B   65536
#define SM2    114688
#define STG    16384

#if TC_OK
// ===========================================================================
// tcgen05 path (round-14: dedicated MMA warp; threads 0-511 stage,
// thread 512 (warp 16) issues MMAs — best known at 537us)
// ===========================================================================
#define TC_ALLOC(sm, n)  asm volatile("tcgen05.alloc.cta_group::1.sync.aligned.shared::cta.b32 [%0], %1;" :: "r"(sm), "r"(n) : "memory")
#define TC_DEALLOC(tb,n) asm volatile("tcgen05.dealloc.cta_group::1.sync.aligned.b32 %0, %1;" :: "r"(tb), "r"(n))
#define TC_RELINQ()      asm volatile("tcgen05.relinquish_alloc_permit.cta_group::1.sync.aligned;")
#define TC_COMMIT(bar)   asm volatile("tcgen05.commit.cta_group::1.mbarrier::arrive::one.shared::cluster.b64 [%0];" :: "r"(bar) : "memory")
#define TC_FENCE_AFTER()  asm volatile("tcgen05.fence::after_thread_sync;" ::: "memory")
#define TC_FENCE_BEFORE() asm volatile("tcgen05.fence::before_thread_sync;" ::: "memory")
#define TC_WAIT_LD()      asm volatile("tcgen05.wait::ld.sync.aligned;" ::: "memory")
#define FENCE_ASYNC()     asm volatile("fence.proxy.async.shared::cta;" ::: "memory")
#define MBAR_INIT(a, c)  asm volatile("mbarrier.init.shared.b64 [%0], %1;" :: "r"(a), "r"(c) : "memory")
#define MBAR_INVAL(a)    asm volatile("mbarrier.inval.shared.b64 [%0];" :: "r"(a) : "memory")
#define MBAR_ARRIVE(a)   asm volatile("mbarrier.arrive.release.cta.shared::cta.b64 _, [%0];" :: "r"(a) : "memory")

#define MBAR_WAIT(addr, par) do {                                              \
    unsigned _m = (unsigned)(addr), _p = (unsigned)(par), _d;                  \
    asm volatile("{\n\t.reg .pred p;\n\t"                                      \
        "mbarrier.try_wait.parity.acquire.cta.shared::cta.b64 p, [%1], %2;\n\t"\
        "selp.b32 %0,1,0,p;\n\t}" : "=r"(_d) : "r"(_m), "r"(_p) : "memory");   \
    if (!_d) {                                                                 \
        asm volatile("{\n\t.reg .pred P1;\n\t"                                 \
        "WL_%=:\n\t"                                                           \
        "mbarrier.try_wait.parity.acquire.cta.shared::cta.b64 P1, [%0], %1, 0x989680;\n\t" \
        "@P1 bra.uni WD_%=;\n\t"                                               \
        "bra.uni WL_%=;\n\t"                                                   \
        "WD_%=:\n\t}" :: "r"(_m), "r"(_p) : "memory");                         \
    }                                                                          \
} while (0)

#define TC_LD32(r, ta) \
    asm volatile( \
        "tcgen05.ld.sync.aligned.32x32b.x32.b32 " \
        "{%0, %1, %2, %3, %4, %5, %6, %7, " \
        " %8, %9, %10, %11, %12, %13, %14, %15, " \
        " %16, %17, %18, %19, %20, %21, %22, %23, " \
        " %24, %25, %26, %27, %28, %29, %30, %31}, [%32];" \
        : "=r"((r)[0]),  "=r"((r)[1]),  "=r"((r)[2]),  "=r"((r)[3]), \
          "=r"((r)[4]),  "=r"((r)[5]),  "=r"((r)[6]),  "=r"((r)[7]), \
          "=r"((r)[8]),  "=r"((r)[9]),  "=r"((r)[10]), "=r"((r)[11]), \
          "=r"((r)[12]), "=r"((r)[13]), "=r"((r)[14]), "=r"((r)[15]), \
          "=r"((r)[16]), "=r"((r)[17]), "=r"((r)[18]), "=r"((r)[19]), \
          "=r"((r)[20]), "=r"((r)[21]), "=r"((r)[22]), "=r"((r)[23]), \
          "=r"((r)[24]), "=r"((r)[25]), "=r"((r)[26]), "=r"((r)[27]), \
          "=r"((r)[28]), "=r"((r)[29]), "=r"((r)[30]), "=r"((r)[31]) \
        : "r"(ta))

// idesc: dtype=F32, FP16 inputs, N=128, M=128
#define IDESC_F16 ((1u << 4) | (16u << 17) | (8u << 24))

__device__ __forceinline__ void mma_f16_ss(unsigned d, unsigned long long a,
                                           unsigned long long b, unsigned en) {
    asm volatile("{\n\t.reg .pred p;\n\tsetp.ne.u32 p, %4, 0;\n\t"
        "tcgen05.mma.cta_group::1.kind::f16 [%0], %1, %2, %3, {%5,%5,%5,%5}, p;\n\t}"
        :: "r"(d), "l"(a), "l"(b), "r"(IDESC_F16), "r"(en), "r"(0u) : "memory");
}
__device__ __forceinline__ unsigned long long make_desc(unsigned addr) {
    return ((unsigned long long)2 << 61) | ((unsigned long long)1 << 46)
         | ((unsigned long long)64 << 32) | ((unsigned long long)1 << 16)
         | ((addr >> 4) & 0x3FFFu);
}

// free barriers at sb+8/16/24 (count 1, flipped by tcgen05.commit)
// ready barriers at sb+32/40/48 (count 512, staging threads only)
__global__ __launch_bounds__(544) void mma_gemm1(
    const int* __restrict__ gp, const float* __restrict__ gsc,
    const int* __restrict__ up, const float* __restrict__ usc,
    const int* __restrict__ sgp, const float* __restrict__ sgs,
    const int* __restrict__ sup, const float* __restrict__ sus) {
    constexpr int NC = H_ / 64;   // 32
    extern __shared__ char smem[];
    const int tid = threadIdx.x, wid = tid >> 5, lid = tid & 31;
    const int j0 = blockIdx.x * 128;
    const int by = blockIdx.y;
    const bool XP = by < E_;
    const int e  = XP ? by : 0;
    const int m0 = XP ? 0 : (by - E_) * 128;
    const int nrows = XP ? g_cnt[e] : 128;
    if (nrows == 0) return;

    unsigned sb = smem_u32(smem);
    if (wid == 0) TC_ALLOC(sb, 256);
    if (tid == 0) {
        MBAR_INIT(sb + 8, 1);  MBAR_INIT(sb + 16, 1); MBAR_INIT(sb + 24, 1);
        MBAR_INIT(sb + 32, 512); MBAR_INIT(sb + 40, 512); MBAR_INIT(sb + 48, 512);
    }
    __syncthreads();
    unsigned tb;
    asm("ld.shared.b32 %0, [%1];" : "=r"(tb) : "r"(sb));

    if (tid < 512) {
        // ------------------ staging threads ------------------
        const int lrow = tid >> 2, lq = tid & 3;
        const __half* arow;
        if (XP) {
            int tok = (lrow < nrows) ? g_slotTok[e * C_ + lrow] : 0;
            arow = g_xh + (size_t)tok * H_;
        } else {
            arow = g_xh + (size_t)(m0 + lrow) * H_;
        }
        const size_t wr0 = ((size_t)(XP ? e * I_ : 0) + j0 + lrow) * (H_ / 8) + lq * 2;
        const int* gpr = (XP ? gp : sgp) + wr0;
        const int* upr = (XP ? up : sup) + wr0;
        const size_t sc0 = (size_t)(XP ? e * (H_ / GS_) * I_ : 0) + j0 + lrow;
        const float* gsp = (XP ? gsc : sgs) + sc0;
        const float* usp = (XP ? usc : sus) + sc0;
        const int bo = lrow * 128 + lq * 32;
        const __half* asrc0 = arow + lq * 16;

        // prologue: B(0) slot0; A(0) stage0; B(1) slot1
        cpa8(sb + G1_PG + tid * 8, gpr);
        cpa8(sb + G1_PU + tid * 8, upr);
        CP_COMMIT();
        cpa16(sb + G1_A + swoff(bo),      asrc0);
        cpa16(sb + G1_A + swoff(bo + 16), asrc0 + 8);
        CP_COMMIT();
        cpa8(sb + G1_PG + 4096 + tid * 8, gpr + 8);
        cpa8(sb + G1_PU + 4096 + tid * 8, upr + 8);
        CP_COMMIT();
        unsigned sg2 = pack_sc(gsp[0]), su2 = pack_sc(usp[0]);

        for (int c = 0; c < NC; c++) {
            const int st = c % 3;
            unsigned sg2N = sg2, su2N = su2;
            if (c + 1 < NC) {
                sg2N = pack_sc(gsp[(size_t)((c + 1) >> 1) * I_]);
                su2N = pack_sc(usp[(size_t)((c + 1) >> 1) * I_]);
            }
            if (c >= 2) {
                int ws = (c - 2) % 3, wp2 = ((c - 2) / 3) & 1;
                MBAR_WAIT(sb + 8 + 8 * ws, wp2);  // MMA(c-2) done -> stage free
            }
            if (c + 1 < NC) {
                unsigned adst = sb + G1_A + ((c + 1) % 3) * STG;
                const __half* asrc = asrc0 + (c + 1) * 64;
                cpa16(adst + swoff(bo),      asrc);
                cpa16(adst + swoff(bo + 16), asrc + 8);
            }
            CP_COMMIT();
            CP_WAIT(2);   // B(c) and A(c) landed (this thread's)
            int2 wg = *(const int2*)(smem + G1_PG + (c & 1) * 4096 + tid * 8);
            int2 wu = *(const int2*)(smem + G1_PU + (c & 1) * 4096 + tid * 8);
            char* Bg = smem + G1_BG + st * STG;
            char* Bu = smem + G1_BU + st * STG;
            st_sw(Bg, bo + 0,  dec8p((unsigned)wg.x, sg2));
            st_sw(Bg, bo + 16, dec8p((unsigned)wg.y, sg2));
            st_sw(Bu, bo + 0,  dec8p((unsigned)wu.x, su2));
            st_sw(Bu, bo + 16, dec8p((unsigned)wu.y, su2));
            if (c + 2 < NC) {
                cpa8(sb + G1_PG + (c & 1) * 4096 + tid * 8, gpr + (c + 2) * 8);
                cpa8(sb + G1_PU + (c & 1) * 4096 + tid * 8, upr + (c + 2) * 8);
            }
            CP_COMMIT();
            FENCE_ASYNC();
            MBAR_ARRIVE(sb + 32 + 8 * st);      // staging(c) done (this thread)
            sg2 = sg2N; su2 = su2N;
        }
        {
            const int ls = (NC - 1) % 3;
            MBAR_WAIT(sb + 8 + 8 * ls, (((NC - 1) - ls) / 3) & 1);
        }
    } else if (tid == 512) {
        // ------------------ MMA warp (elected thread) ------------------
        for (int c = 0; c < NC; c++) {
            const int st = c % 3;
            MBAR_WAIT(sb + 32 + 8 * st, (c / 3) & 1);   // all 512 staged
            unsigned long long ad = make_desc(sb + G1_A  + st * STG);
            unsigned long long gd = make_desc(sb + G1_BG + st * STG);
            unsigned long long ud = make_desc(sb + G1_BU + st * STG);
            #pragma unroll
            for (int ks = 0; ks < 4; ks++) {
                unsigned en = (c > 0 || ks > 0) ? 1u : 0u;
                mma_f16_ss(tb,       ad + ks * 2, gd + ks * 2, en);
                mma_f16_ss(tb + 128, ad + ks * 2, ud + ks * 2, en);
            }
            TC_COMMIT(sb + 8 + 8 * st);
        }
    }
    TC_FENCE_AFTER();

    // epilogue: warps 0-15 only; warp 16 just syncs
    if (wid < 16) {
        const int r = (wid & 3) * 32 + lid;
        const int cb = (wid >> 2) * 32;
        bool valid = XP ? (r < nrows) : true;
        __half* drow = XP ? (g_hbuf + ((size_t)e * C_ + r) * I_)
                          : (g_hsh  + (size_t)(m0 + r) * I_);
        unsigned gr[32], ur[32];
        TC_LD32(gr, tb + cb);
        TC_LD32(ur, tb + 128 + cb);
        TC_WAIT_LD();
        if (valid) {
            #pragma unroll
            for (int q = 0; q < 4; q++) {
                float v[8];
                #pragma unroll
                for (int t = 0; t < 8; t++) {
                    int j = q * 8 + t;
                    float gv = __uint_as_float(gr[j]);
                    float uv = __uint_as_float(ur[j]);
                    v[t] = gv / (1.f + __expf(-gv)) * uv;
                }
                uint4 o;
                o.x = h2u(__float22half2_rn(make_float2(v[0], v[1])));
                o.y = h2u(__float22half2_rn(make_float2(v[2], v[3])));
                o.z = h2u(__float22half2_rn(make_float2(v[4], v[5])));
                o.w = h2u(__float22half2_rn(make_float2(v[6], v[7])));
                *reinterpret_cast<uint4*>(drow + j0 + cb + q * 8) = o;
            }
        }
        TC_FENCE_BEFORE();
    }
    __syncthreads();
    if (tid == 0) {
        MBAR_INVAL(sb + 8);  MBAR_INVAL(sb + 16); MBAR_INVAL(sb + 24);
        MBAR_INVAL(sb + 32); MBAR_INVAL(sb + 40); MBAR_INVAL(sb + 48);
    }
    __syncthreads();
    if (wid == 0) { TC_RELINQ(); TC_DEALLOC(tb, 256); }
}

__global__ __launch_bounds__(544) void mma_gemm2(
    const int* __restrict__ dp, const float* __restrict__ dsc,
    const int* __restrict__ sdp, const float* __restrict__ sds,
    float* __restrict__ y) {
    constexpr int NC = I_ / 64;   // 24
    extern __shared__ char smem[];
    const int tid = threadIdx.x, wid = tid >> 5, lid = tid & 31;
    const int n0 = blockIdx.x * 128;
    const int by = blockIdx.y;
    const bool XP = by < E_;
    const int e  = XP ? by : 0;
    const int m0 = XP ? 0 : (by - E_) * 128;
    const int nrows = XP ? g_cnt[e] : 128;
    if (nrows == 0) return;

    unsigned sb = smem_u32(smem);
    if (wid == 0) TC_ALLOC(sb, 128);
    if (tid == 0) {
        MBAR_INIT(sb + 8, 1);  MBAR_INIT(sb + 16, 1); MBAR_INIT(sb + 24, 1);
        MBAR_INIT(sb + 32, 512); MBAR_INIT(sb + 40, 512); MBAR_INIT(sb + 48, 512);
    }
    __syncthreads();
    unsigned tb;
    asm("ld.shared.b32 %0, [%1];" : "=r"(tb) : "r"(sb));

    if (tid < 512) {
        const int lrow = tid >> 2, lq = tid & 3;
        const __half* arow = XP ? (g_hbuf + ((size_t)e * C_ + lrow) * I_)
                                : (g_hsh  + (size_t)(m0 + lrow) * I_);
        const int* dpr = (XP ? dp : sdp)
                       + ((size_t)(XP ? e * H_ : 0) + n0 + lrow) * (I_ / 8) + lq * 2;
        const float* dsp = (XP ? dsc : sds)
                         + (size_t)(XP ? e * (I_ / GS_) * H_ : 0) + n0 + lrow;
        const int bo = lrow * 128 + lq * 32;
        const __half* asrc0 = arow + lq * 16;

        // prologue: Bp(0); A(0)->stage0; Bp(1)
        cpa8(sb + G2_PB + tid * 8, dpr);
        CP_COMMIT();
        cpa16(sb + G2_A + swoff(bo),      asrc0);
        cpa16(sb + G2_A + swoff(bo + 16), asrc0 + 8);
        CP_COMMIT();
        cpa8(sb + G2_PB + 4096 + tid * 8, dpr + 8);
        CP_COMMIT();
        unsigned sd2 = pack_sc(dsp[0]);

        for (int c = 0; c < NC; c++) {
            const int st = c % 3;
            unsigned sd2N = sd2;
            if (c + 1 < NC) sd2N = pack_sc(dsp[(size_t)((c + 1) >> 1) * H_]);
            if (c >= 2) {
                int ws = (c - 2) % 3, wp2 = ((c - 2) / 3) & 1;
                MBAR_WAIT(sb + 8 + 8 * ws, wp2);
            }
            if (c + 1 < NC) {
                unsigned adst = sb + G2_A + ((c + 1) % 3) * STG;
                const __half* asrc = asrc0 + (c + 1) * 64;
                cpa16(adst + swoff(bo),      asrc);
                cpa16(adst + swoff(bo + 16), asrc + 8);
            }
            CP_COMMIT();
            CP_WAIT(2);
            int2 wd = *(const int2*)(smem + G2_PB + (c & 1) * 4096 + tid * 8);
            char* Bt = smem + G2_B + st * STG;
            st_sw(Bt, bo + 0,  dec8p((unsigned)wd.x, sd2));
            st_sw(Bt, bo + 16, dec8p((unsigned)wd.y, sd2));
            if (c + 2 < NC)
                cpa8(sb + G2_PB + (c & 1) * 4096 + tid * 8, dpr + (c + 2) * 8);
            CP_COMMIT();
            FENCE_ASYNC();
            MBAR_ARRIVE(sb + 32 + 8 * st);
            sd2 = sd2N;
        }
        {
            const int ls = (NC - 1) % 3;
            MBAR_WAIT(sb + 8 + 8 * ls, (((NC - 1) - ls) / 3) & 1);
        }
    } else if (tid == 512) {
        for (int c = 0; c < NC; c++) {
            const int st = c % 3;
            MBAR_WAIT(sb + 32 + 8 * st, (c / 3) & 1);
            unsigned long long ad = make_desc(sb + G2_A + st * STG);
            unsigned long long bd = make_desc(sb + G2_B + st * STG);
            #pragma unroll
            for (int ks = 0; ks < 4; ks++) {
                unsigned en = (c > 0 || ks > 0) ? 1u : 0u;
                mma_f16_ss(tb, ad + ks * 2, bd + ks * 2, en);
            }
            TC_COMMIT(sb + 8 + 8 * st);
        }
    }
    TC_FENCE_AFTER();

    if (wid < 16) {
        const int r = (wid & 3) * 32 + lid;
        const int cb = (wid >> 2) * 32;
        bool valid = XP ? (r < nrows) : true;
        int tok = 0; float wgt = 0.f;
        if (XP) { if (valid) { tok = g_slotTok[e * C_ + r]; wgt = g_slotW[e * C_ + r]; } }
        else    { tok = m0 + r; wgt = 1.f; }
        unsigned dr[32];
        TC_LD32(dr, tb + cb);
        TC_WAIT_LD();
        if (valid) {
            float* dst = y + (size_t)tok * H_ + n0 + cb;
            #pragma unroll
            for (int j = 0; j < 32; j += 4) {
                float v0 = wgt * __uint_as_float(dr[j]);
                float v1 = wgt * __uint_as_float(dr[j + 1]);
                float v2 = wgt * __uint_as_float(dr[j + 2]);
                float v3 = wgt * __uint_as_float(dr[j + 3]);
                asm volatile("red.global.add.v4.f32 [%0], {%1,%2,%3,%4};"
                    :: "l"(dst + j), "f"(v0), "f"(v1), "f"(v2), "f"(v3) : "memory");
            }
        }
        TC_FENCE_BEFORE();
    }
    __syncthreads();
    if (tid == 0) {
        MBAR_INVAL(sb + 8);  MBAR_INVAL(sb + 16); MBAR_INVAL(sb + 24);
        MBAR_INVAL(sb + 32); MBAR_INVAL(sb + 40); MBAR_INVAL(sb + 48);
    }
    __syncthreads();
    if (wid == 0) { TC_RELINQ(); TC_DEALLOC(tb, 128); }
}

#else  // !TC_OK
// ===========================================================================
// fallback: mma.sync (compiles for plain sm_103; never selected on GB300 —
// first 256 threads do the work, syncs stay block-wide)
// ===========================================================================
__device__ __forceinline__ void ldm_x4(unsigned r[4], unsigned a) {
    asm volatile("ldmatrix.sync.aligned.m8n8.x4.shared.b16 {%0,%1,%2,%3}, [%4];"
                 : "=r"(r[0]), "=r"(r[1]), "=r"(r[2]), "=r"(r[3]) : "r"(a));
}
__device__ __forceinline__ void ldm_x2(unsigned r[2], unsigned a) {
    asm volatile("ldmatrix.sync.aligned.m8n8.x2.shared.b16 {%0,%1}, [%2];"
                 : "=r"(r[0]), "=r"(r[1]) : "r"(a));
}
__device__ __forceinline__ void mma16816(float* d, const unsigned* a, const unsigned* b) {
    asm volatile("mma.sync.aligned.m16n8k16.row.col.f32.f16.f16.f32 "
        "{%0,%1,%2,%3}, {%4,%5,%6,%7}, {%8,%9}, {%0,%1,%2,%3};"
        : "+f"(d[0]), "+f"(d[1]), "+f"(d[2]), "+f"(d[3])
        : "r"(a[0]), "r"(a[1]), "r"(a[2]), "r"(a[3]), "r"(b[0]), "r"(b[1]));
}

__global__ __launch_bounds__(544) void mma_gemm1(
    const int* __restrict__ gp, const float* __restrict__ gsc,
    const int* __restrict__ up, const float* __restrict__ usc,
    const int* __restrict__ sgp, const float* __restrict__ sgs,
    const int* __restrict__ sup, const float* __restrict__ sus) {
    constexpr int NC = H_ / 64;
    extern __shared__ char smem[];
    const int tid = threadIdx.x;
    const bool act = tid < 256;
    const int t2 = tid & 255, wid = t2 >> 5, lane = t2 & 31;
    const int j0 = blockIdx.x * 128;
    const int by = blockIdx.y;
    const bool XP = by < E_;
    const int e  = XP ? by : 0;
    const int m0 = XP ? 0 : (by - E_) * 128;
    const int nrows = XP ? g_cnt[e] : 128;
    if (nrows == 0) return;

    unsigned sb = smem_u32(smem);
    const unsigned Ab = sb + G1_A, Bgb = sb + G1_BG, Bub = sb + G1_BU;
    const int lrow = t2 >> 1, lh = t2 & 1;
    const __half* arow;
    if (XP) {
        int tok = (lrow < nrows) ? g_slotTok[e * C_ + lrow] : 0;
        arow = g_xh + (size_t)tok * H_;
    } else {
        arow = g_xh + (size_t)(m0 + lrow) * H_;
    }
    const size_t wr0 = ((size_t)(XP ? e * I_ : 0) + j0 + lrow) * (H_ / 8) + lh * 4;
    const int* gpr = (XP ? gp : sgp) + wr0;
    const int* upr = (XP ? up : sup) + wr0;
    const size_t sc0 = (size_t)(XP ? e * (H_ / GS_) * I_ : 0) + j0 + lrow;
    const float* gsp = (XP ? gsc : sgs) + sc0;
    const float* usp = (XP ? usc : sus) + sc0;
    const int bo = lrow * 128 + lh * 64;
    const int wm = wid >> 2, wn = wid & 3;

    float ag[4][4][4], au[4][4][4];
    #pragma unroll
    for (int i = 0; i < 4; i++)
        #pragma unroll
        for (int j = 0; j < 4; j++)
            #pragma unroll
            for (int q = 0; q < 4; q++) { ag[i][j][q] = 0.f; au[i][j][q] = 0.f; }

    for (int c = 0; c < NC; c++) {
        int kk = c * 64;
        if (act) {
            stage_A_f16(smem + G1_A, arow, kk, bo, lh);
            stage_B4(smem + G1_BG, *(const int4*)(gpr + (kk >> 3)),
                     pack_sc(gsp[(size_t)(kk >> 7) * I_]), bo);
            stage_B4(smem + G1_BU, *(const int4*)(upr + (kk >> 3)),
                     pack_sc(usp[(size_t)(kk >> 7) * I_]), bo);
        }
        __syncthreads();
        if (act) {
            #pragma unroll
            for (int ks = 0; ks < 4; ks++) {
                unsigned af[4][4];
                #pragma unroll
                for (int mt = 0; mt < 4; mt++)
                    ldm_x4(af[mt], swadr(Ab, wm * 64 + mt * 16 + (lane & 15),
                                         ks * 32 + (lane >> 4) * 16));
                #pragma unroll
                for (int nt = 0; nt < 4; nt++) {
                    int brow = wn * 32 + nt * 8 + (lane & 7);
                    int bcol = ks * 32 + ((lane >> 3) & 1) * 16;
                    unsigned bg[2], bu[2];
                    ldm_x2(bg, swadr(Bgb, brow, bcol));
                    ldm_x2(bu, swadr(Bub, brow, bcol));
                    #pragma unroll
                    for (int mt = 0; mt < 4; mt++) {
                        mma16816(ag[mt][nt], af[mt], bg);
                        mma16816(au[mt][nt], af[mt], bu);
                    }
                }
            }
        }
        __syncthreads();
    }
    if (act) {
        const int g = lane >> 2, cq = lane & 3;
        #pragma unroll
        for (int mt = 0; mt < 4; mt++)
            #pragma unroll
            for (int nt = 0; nt < 4; nt++) {
                int nn = j0 + wn * 32 + nt * 8 + cq * 2;
                #pragma unroll
                for (int hrow = 0; hrow < 2; hrow++) {
                    int r = wm * 64 + mt * 16 + g + hrow * 8;
                    if (XP && r >= nrows) continue;
                    float g0 = ag[mt][nt][hrow * 2], g1 = ag[mt][nt][hrow * 2 + 1];
                    float u0 = au[mt][nt][hrow * 2], u1 = au[mt][nt][hrow * 2 + 1];
                    float v0 = g0 / (1.f + expf(-g0)) * u0;
                    float v1 = g1 / (1.f + expf(-g1)) * u1;
                    __half* dst = (XP ? g_hbuf + ((size_t)e * C_ + r) * I_
                                      : g_hsh + (size_t)(m0 + r) * I_) + nn;
                    *reinterpret_cast<__half2*>(dst) =
                        __float22half2_rn(make_float2(v0, v1));
                }
            }
    }
}

__global__ __launch_bounds__(544) void mma_gemm2(
    const int* __restrict__ dp, const float* __restrict__ dsc,
    const int* __restrict__ sdp, const float* __restrict__ sds,
    float* __restrict__ y) {
    constexpr int NC = I_ / 64;
    extern __shared__ char smem[];
    const int tid = threadIdx.x;
    const bool act = tid < 256;
    const int t2 = tid & 255, wid = t2 >> 5, lane = t2 & 31;
    const int n0 = blockIdx.x * 128;
    const int by = blockIdx.y;
    const bool XP = by < E_;
    const int e  = XP ? by : 0;
    const int m0 = XP ? 0 : (by - E_) * 128;
    const int nrows = XP ? g_cnt[e] : 128;
    if (nrows == 0) return;

    unsigned sb = smem_u32(smem);
    const unsigned Ab = sb + G2_A, Bb = sb + G2_B;
    const int lrow = t2 >> 1, lh = t2 & 1;
    const __half* arow = XP ? (g_hbuf + ((size_t)e * C_ + lrow) * I_)
                            : (g_hsh  + (size_t)(m0 + lrow) * I_);
    const int* dpr = (XP ? dp : sdp)
                   + ((size_t)(XP ? e * H_ : 0) + n0 + lrow) * (I_ / 8) + lh * 4;
    const float* dsp = (XP ? dsc : sds)
                     + (size_t)(XP ? e * (I_ / GS_) * H_ : 0) + n0 + lrow;
    const int bo = lrow * 128 + lh * 64;
    const int wm = wid >> 2, wn = wid & 3;

    float acc[4][4][4];
    #pragma unroll
    for (int i = 0; i < 4; i++)
        #pragma unroll
        for (int j = 0; j < 4; j++)
            #pragma unroll
            for (int q = 0; q < 4; q++) acc[i][j][q] = 0.f;

    for (int c = 0; c < NC; c++) {
        int kk = c * 64;
        if (act) {
            stage_A_f16(smem + G2_A, arow, kk, bo, lh);
            stage_B4(smem + G2_B, *(const int4*)(dpr + (kk >> 3)),
                     pack_sc(dsp[(size_t)(kk >> 7) * H_]), bo);
        }
        __syncthreads();
        if (act) {
            #pragma unroll
            for (int ks = 0; ks < 4; ks++) {
                unsigned af[4][4];
                #pragma unroll
                for (int mt = 0; mt < 4; mt++)
                    ldm_x4(af[mt], swadr(Ab, wm * 64 + mt * 16 + (lane & 15),
                                         ks * 32 + (lane >> 4) * 16));
                #pragma unroll
                for (int nt = 0; nt < 4; nt++) {
                    int brow = wn * 32 + nt * 8 + (lane & 7);
                    int bcol = ks * 32 + ((lane >> 3) & 1) * 16;
                    unsigned bf[2];
                    ldm_x2(bf, swadr(Bb, brow, bcol));
                    #pragma unroll
                    for (int mt = 0; mt < 4; mt++)
                        mma16816(acc[mt][nt], af[mt], bf);
                }
            }
        }
        __syncthreads();
    }
    if (act) {
        const int g = lane >> 2, cq = lane & 3;
        #pragma unroll
        for (int mt = 0; mt < 4; mt++)
            #pragma unroll
            for (int hrow = 0; hrow < 2; hrow++) {
                int r = wm * 64 + mt * 16 + g + hrow * 8;
                if (XP && r >= nrows) continue;
                int tok; float wgt;
                if (XP) { tok = g_slotTok[e * C_ + r]; wgt = g_slotW[e * C_ + r]; }
                else    { tok = m0 + r; wgt = 1.f; }
                #pragma unroll
                for (int nt = 0; nt < 4; nt++) {
                    int nn = n0 + wn * 32 + nt * 8 + cq * 2;
                    float* dst = y + (size_t)tok * H_ + nn;
                    atomicAdd(dst,     wgt * acc[mt][nt][hrow * 2]);
                    atomicAdd(dst + 1, wgt * acc[mt][nt][hrow * 2 + 1]);
                }
            }
    }
}
#endif  // TC_OK

// ---------------------------------------------------------------------------
// launch
// ---------------------------------------------------------------------------
extern "C" void kernel_launch(void* const* d_in, const int* in_sizes, int n_in,
                              void* d_out, int out_size) {
    const float* x   = (const float*)d_in[0];
    const float* gw  = (const float*)d_in[1];
    const float* gsc = (const float*)d_in[2];
    const float* usc = (const float*)d_in[3];
    const float* dsc = (const float*)d_in[4];
    const float* sgs = (const float*)d_in[5];
    const float* sus = (const float*)d_in[6];
    const float* sds = (const float*)d_in[7];
    const int*   gpk = (const int*)d_in[8];
    const int*   upk = (const int*)d_in[9];
    const int*   dpk = (const int*)d_in[10];
    const int*   sgp = (const int*)d_in[11];
    const int*   sup = (const int*)d_in[12];
    const int*   sdp = (const int*)d_in[13];
    float* y = (float*)d_out;

    cudaFuncSetAttribute(mma_gemm1, cudaFuncAttributeMaxDynamicSharedMemorySize, SM1);
    cudaFuncSetAttribute(mma_gemm2, cudaFuncAttributeMaxDynamicSharedMemorySize, SM2);

    routing_kernel<<<T_ / 8, 256>>>(x, gw);
    dispatch_kernel<<<2, 1024>>>();
    xcvt_zero_kernel<<<(T_ * H_ / 4) / 512, 512>>>((const float4*)x, (float4*)y);

    // stage 1: SwiGLU intermediates (experts y=0..63, shared tiles y=64..71)
    mma_gemm1<<<dim3(I_ / 128, E_ + T_ / 128), 544, SM1>>>(
        gpk, gsc, upk, usc, sgp, sgs, sup, sus);

    // stage 2: down-proj, all paths combine into zeroed y via red.v4
    mma_gemm2<<<dim3(H_ / 128, E_ + T_ / 128), 544, SM2>>>(
        dpk, dsc, sdp, sds, y);
}

// round 17
// speedup vs baseline: 1.0648x; 1.0034x over previous
#include <cuda_runtime.h>
#include <cuda_fp16.h>
#include <math.h>

#define E_   64
#define KTOP 4
#define H_   2048
#define I_   1536
#define GS_  128
#define T_   1024
#define C_   128

#if defined(__CUDA_ARCH__) && !defined(__CUDA_ARCH_FEAT_SM103_ALL) && !defined(__CUDA_ARCH_FEAT_SM100_ALL)
#define TC_OK 0
#else
#define TC_OK 1
#endif

// ---------------------------------------------------------------------------
// common helpers
// ---------------------------------------------------------------------------
__device__ __forceinline__ unsigned smem_u32(const void* p) {
    unsigned a;
    asm("{ .reg .u64 t; cvta.to.shared.u64 t, %1; cvt.u32.u64 %0, t; }" : "=r"(a) : "l"(p));
    return a;
}
__device__ __forceinline__ unsigned h2u(__half2 h) {
    return *reinterpret_cast<unsigned*>(&h);
}
__device__ __forceinline__ unsigned swoff(int off) {
    return (unsigned)(off ^ ((off >> 3) & 0x70));
}
__device__ __forceinline__ void st_sw(char* base, int off, uint4 v) {
    *reinterpret_cast<uint4*>(base + swoff(off)) = v;
}
__device__ __forceinline__ unsigned swadr(unsigned base, int row, int col) {
    return base + swoff(row * 128 + col);
}
__device__ __forceinline__ unsigned pack_sc(float s) {
    return h2u(__float2half2_rn(s));
}

__device__ __forceinline__ void cpa16(unsigned dst, const void* src) {
    asm volatile("cp.async.ca.shared.global [%0], [%1], 16;" :: "r"(dst), "l"(src));
}
__device__ __forceinline__ void cpa8(unsigned dst, const void* src) {
    asm volatile("cp.async.ca.shared.global [%0], [%1], 8;" :: "r"(dst), "l"(src));
}
#define CP_COMMIT() asm volatile("cp.async.commit_group;" ::: "memory")
#define CP_WAIT(n)  asm volatile("cp.async.wait_group %0;" :: "n"(n) : "memory")

// FP4 E2M1 x8 -> 8 fp16 via PRMT tables; sc2 = half2(scale, scale)
__device__ __forceinline__ uint4 dec8p(unsigned w, unsigned sc2) {
    const unsigned tLo = 0x3E3C3800u, tHi = 0x46444240u;
    unsigned m0, m1;
    asm("prmt.b32 %0,%1,%2,%3;" : "=r"(m0) : "r"(tLo), "r"(tHi), "r"(w & 0x7777u));
    asm("prmt.b32 %0,%1,%2,%3;" : "=r"(m1) : "r"(tLo), "r"(tHi), "r"((w >> 16) & 0x7777u));
    unsigned q4 = (w << 4) & 0x80808080u;
    unsigned q0 = w & 0x80808080u;
    unsigned r[4];
    #pragma unroll
    for (int p = 0; p < 4; p++) {
        unsigned mag  = (p < 2) ? m0 : m1;
        unsigned mctl = (p & 1) ? 0x3424u : 0x1404u;
        unsigned me, se;
        asm("prmt.b32 %0,%1,%2,%3;" : "=r"(me) : "r"(mag), "r"(0u), "r"(mctl));
        unsigned sctl = 0x4000u + (unsigned)p * 0x1010u;
        asm("prmt.b32 %0,%1,%2,%3;" : "=r"(se) : "r"(q4), "r"(q0), "r"(sctl));
        unsigned v = me | (se & 0x80008000u);
        asm("mul.rn.f16x2 %0,%1,%2;" : "=r"(r[p]) : "r"(v), "r"(sc2));
    }
    return make_uint4(r[0], r[1], r[2], r[3]);
}

// fallback-path helpers (256-thread mappings)
__device__ __forceinline__ void stage_B4(char* Bt, int4 w, unsigned sc2, int bo) {
    st_sw(Bt, bo + 0,  dec8p((unsigned)w.x, sc2));
    st_sw(Bt, bo + 16, dec8p((unsigned)w.y, sc2));
    st_sw(Bt, bo + 32, dec8p((unsigned)w.z, sc2));
    st_sw(Bt, bo + 48, dec8p((unsigned)w.w, sc2));
}
__device__ __forceinline__ void stage_A_f16(char* At, const __half* arow, int kk,
                                            int bo, int lh) {
    #pragma unroll
    for (int q = 0; q < 4; q++) {
        uint4 v = *reinterpret_cast<const uint4*>(arow + kk + lh * 32 + q * 8);
        st_sw(At, bo + q * 16, v);
    }
}

// ---------------------------------------------------------------------------
// scratch
// ---------------------------------------------------------------------------
__device__ int    g_ti[T_ * KTOP];
__device__ float  g_tw[T_ * KTOP];
__device__ int    g_cnt[E_];
__device__ int    g_slotTok[E_ * C_];
__device__ float  g_slotW[E_ * C_];
__device__ __half g_hbuf[(size_t)E_ * C_ * I_];
__device__ __half g_hsh[(size_t)T_ * I_];
__device__ __half g_xh[(size_t)T_ * H_];

// ---------------------------------------------------------------------------
// routing v2: 4 tokens/block, x cached in smem, 2-thread split dots
// ---------------------------------------------------------------------------
__global__ __launch_bounds__(512) void routing_kernel(
    const float* __restrict__ x, const float* __restrict__ gw) {
    __shared__ float4 xs[4][512];   // 4 rows x 2048 floats = 32 KB
    __shared__ float  lg[4][E_];
    const int tid  = threadIdx.x;
    const int tok0 = blockIdx.x * 4;

    // load 4 x-rows to smem: 2048 float4, 4 per thread
    #pragma unroll
    for (int i = 0; i < 4; i++) {
        int idx = tid + i * 512;
        int row = idx >> 9, col = idx & 511;
        xs[row][col] = reinterpret_cast<const float4*>(
            x + (size_t)(tok0 + row) * H_)[col];
    }
    __syncthreads();

    // pair p = tid>>1 covers (tk, e); half = tid&1 covers 1024 dims
    const int p  = tid >> 1, hf = tid & 1;
    const int tk = p >> 6,   e  = p & 63;
    const float4* wr = reinterpret_cast<const float4*>(gw + (size_t)e * H_) + hf * 256;
    const float4* xr = &xs[tk][hf * 256];
    float acc = 0.f;
    #pragma unroll 4
    for (int h = 0; h < 256; h++) {
        float4 a = xr[h];
        float4 b = wr[h];
        acc += a.x * b.x + a.y * b.y + a.z * b.z + a.w * b.w;
    }
    acc += __shfl_xor_sync(0xffffffffu, acc, 1);
    if (hf == 0) lg[tk][e] = acc;
    __syncthreads();

    if (tid < 4) {
        int t = tok0 + tid;
        unsigned long long used = 0ull;
        float v[KTOP]; int id[KTOP];
        #pragma unroll
        for (int k = 0; k < KTOP; k++) {
            float best = -INFINITY; int bi = 0;
            for (int ee = 0; ee < E_; ee++)
                if (!((used >> ee) & 1ull) && lg[tid][ee] > best) { best = lg[tid][ee]; bi = ee; }
            v[k] = best; id[k] = bi; used |= 1ull << bi;
        }
        float mx = v[0], w[KTOP], sum = 0.f;
        #pragma unroll
        for (int k = 0; k < KTOP; k++) { w[k] = expf(v[k] - mx); sum += w[k]; }
        #pragma unroll
        for (int k = 0; k < KTOP; k++) {
            g_ti[t * KTOP + k] = id[k];
            g_tw[t * KTOP + k] = w[k] / sum;
        }
    }
}

__global__ void dispatch_kernel() {
    __shared__ int sti[T_ * KTOP];
    int tid = threadIdx.x;
    for (int i = tid; i < T_ * KTOP; i += blockDim.x) sti[i] = g_ti[i];
    __syncthreads();
    int wid = tid >> 5, lane = tid & 31;
    int e = blockIdx.x * (blockDim.x >> 5) + wid;
    if (e < E_) {
        int cnt = 0;
        for (int base = 0; base < T_ * KTOP; base += 32) {
            int a = base + lane;
            bool m = (sti[a] == e);
            unsigned msk = __ballot_sync(0xffffffffu, m);
            if (m) {
                int c = cnt + __popc(msk & ((1u << lane) - 1u));
                if (c < C_) {
                    g_slotTok[e * C_ + c] = a >> 2;
                    g_slotW[e * C_ + c]   = g_tw[a];
                }
            }
            cnt += __popc(msk);
        }
        if (lane == 0) g_cnt[e] = cnt < C_ ? cnt : C_;
    }
}

// fused: zero y and convert x -> fp16
__global__ void xcvt_zero_kernel(const float4* __restrict__ x, float4* __restrict__ y) {
    size_t i = (size_t)blockIdx.x * blockDim.x + threadIdx.x;
    y[i] = make_float4(0.f, 0.f, 0.f, 0.f);
    float4 v = x[i];
    uint2 o;
    o.x = h2u(__float22half2_rn(make_float2(v.x, v.y)));
    o.y = h2u(__float22half2_rn(make_float2(v.z, v.w)));
    reinterpret_cast<uint2*>(g_xh)[i] = o;
}

// SMEM layouts (round-11 proven; disjoint, tiles 1024-aligned)
#define G1_PG  64
#define G1_PU  8256
#define G1_A   17408
#define G1_BG  66560
#define G1_BU  115712
#define SM1    164864
#define G2_PB  64
#define G2_A   16384
#define G2_B   65536
#define SM2    114688
#define STG    16384

#if TC_OK
// ===========================================================================
// tcgen05 path (round-14: dedicated MMA warp; threads 0-511 stage,
// thread 512 (warp 16) issues MMAs — best known at 537us)
// ===========================================================================
#define TC_ALLOC(sm, n)  asm volatile("tcgen05.alloc.cta_group::1.sync.aligned.shared::cta.b32 [%0], %1;" :: "r"(sm), "r"(n) : "memory")
#define TC_DEALLOC(tb,n) asm volatile("tcgen05.dealloc.cta_group::1.sync.aligned.b32 %0, %1;" :: "r"(tb), "r"(n))
#define TC_RELINQ()      asm volatile("tcgen05.relinquish_alloc_permit.cta_group::1.sync.aligned;")
#define TC_COMMIT(bar)   asm volatile("tcgen05.commit.cta_group::1.mbarrier::arrive::one.shared::cluster.b64 [%0];" :: "r"(bar) : "memory")
#define TC_FENCE_AFTER()  asm volatile("tcgen05.fence::after_thread_sync;" ::: "memory")
#define TC_FENCE_BEFORE() asm volatile("tcgen05.fence::before_thread_sync;" ::: "memory")
#define TC_WAIT_LD()      asm volatile("tcgen05.wait::ld.sync.aligned;" ::: "memory")
#define FENCE_ASYNC()     asm volatile("fence.proxy.async.shared::cta;" ::: "memory")
#define MBAR_INIT(a, c)  asm volatile("mbarrier.init.shared.b64 [%0], %1;" :: "r"(a), "r"(c) : "memory")
#define MBAR_INVAL(a)    asm volatile("mbarrier.inval.shared.b64 [%0];" :: "r"(a) : "memory")
#define MBAR_ARRIVE(a)   asm volatile("mbarrier.arrive.release.cta.shared::cta.b64 _, [%0];" :: "r"(a) : "memory")

#define MBAR_WAIT(addr, par) do {                                              \
    unsigned _m = (unsigned)(addr), _p = (unsigned)(par), _d;                  \
    asm volatile("{\n\t.reg .pred p;\n\t"                                      \
        "mbarrier.try_wait.parity.acquire.cta.shared::cta.b64 p, [%1], %2;\n\t"\
        "selp.b32 %0,1,0,p;\n\t}" : "=r"(_d) : "r"(_m), "r"(_p) : "memory");   \
    if (!_d) {                                                                 \
        asm volatile("{\n\t.reg .pred P1;\n\t"                                 \
        "WL_%=:\n\t"                                                           \
        "mbarrier.try_wait.parity.acquire.cta.shared::cta.b64 P1, [%0], %1, 0x989680;\n\t" \
        "@P1 bra.uni WD_%=;\n\t"                                               \
        "bra.uni WL_%=;\n\t"                                                   \
        "WD_%=:\n\t}" :: "r"(_m), "r"(_p) : "memory");                         \
    }                                                                          \
} while (0)

#define TC_LD32(r, ta) \
    asm volatile( \
        "tcgen05.ld.sync.aligned.32x32b.x32.b32 " \
        "{%0, %1, %2, %3, %4, %5, %6, %7, " \
        " %8, %9, %10, %11, %12, %13, %14, %15, " \
        " %16, %17, %18, %19, %20, %21, %22, %23, " \
        " %24, %25, %26, %27, %28, %29, %30, %31}, [%32];" \
        : "=r"((r)[0]),  "=r"((r)[1]),  "=r"((r)[2]),  "=r"((r)[3]), \
          "=r"((r)[4]),  "=r"((r)[5]),  "=r"((r)[6]),  "=r"((r)[7]), \
          "=r"((r)[8]),  "=r"((r)[9]),  "=r"((r)[10]), "=r"((r)[11]), \
          "=r"((r)[12]), "=r"((r)[13]), "=r"((r)[14]), "=r"((r)[15]), \
          "=r"((r)[16]), "=r"((r)[17]), "=r"((r)[18]), "=r"((r)[19]), \
          "=r"((r)[20]), "=r"((r)[21]), "=r"((r)[22]), "=r"((r)[23]), \
          "=r"((r)[24]), "=r"((r)[25]), "=r"((r)[26]), "=r"((r)[27]), \
          "=r"((r)[28]), "=r"((r)[29]), "=r"((r)[30]), "=r"((r)[31]) \
        : "r"(ta))

// idesc: dtype=F32, FP16 inputs, N=128, M=128
#define IDESC_F16 ((1u << 4) | (16u << 17) | (8u << 24))

__device__ __forceinline__ void mma_f16_ss(unsigned d, unsigned long long a,
                                           unsigned long long b, unsigned en) {
    asm volatile("{\n\t.reg .pred p;\n\tsetp.ne.u32 p, %4, 0;\n\t"
        "tcgen05.mma.cta_group::1.kind::f16 [%0], %1, %2, %3, {%5,%5,%5,%5}, p;\n\t}"
        :: "r"(d), "l"(a), "l"(b), "r"(IDESC_F16), "r"(en), "r"(0u) : "memory");
}
__device__ __forceinline__ unsigned long long make_desc(unsigned addr) {
    return ((unsigned long long)2 << 61) | ((unsigned long long)1 << 46)
         | ((unsigned long long)64 << 32) | ((unsigned long long)1 << 16)
         | ((addr >> 4) & 0x3FFFu);
}

// free barriers at sb+8/16/24 (count 1, flipped by tcgen05.commit)
// ready barriers at sb+32/40/48 (count 512, staging threads only)
__global__ __launch_bounds__(544) void mma_gemm1(
    const int* __restrict__ gp, const float* __restrict__ gsc,
    const int* __restrict__ up, const float* __restrict__ usc,
    const int* __restrict__ sgp, const float* __restrict__ sgs,
    const int* __restrict__ sup, const float* __restrict__ sus) {
    constexpr int NC = H_ / 64;   // 32
    extern __shared__ char smem[];
    const int tid = threadIdx.x, wid = tid >> 5, lid = tid & 31;
    const int j0 = blockIdx.x * 128;
    const int by = blockIdx.y;
    const bool XP = by < E_;
    const int e  = XP ? by : 0;
    const int m0 = XP ? 0 : (by - E_) * 128;
    const int nrows = XP ? g_cnt[e] : 128;
    if (nrows == 0) return;

    unsigned sb = smem_u32(smem);
    if (wid == 0) TC_ALLOC(sb, 256);
    if (tid == 0) {
        MBAR_INIT(sb + 8, 1);  MBAR_INIT(sb + 16, 1); MBAR_INIT(sb + 24, 1);
        MBAR_INIT(sb + 32, 512); MBAR_INIT(sb + 40, 512); MBAR_INIT(sb + 48, 512);
    }
    __syncthreads();
    unsigned tb;
    asm("ld.shared.b32 %0, [%1];" : "=r"(tb) : "r"(sb));

    if (tid < 512) {
        // ------------------ staging threads ------------------
        const int lrow = tid >> 2, lq = tid & 3;
        const __half* arow;
        if (XP) {
            int tok = (lrow < nrows) ? g_slotTok[e * C_ + lrow] : 0;
            arow = g_xh + (size_t)tok * H_;
        } else {
            arow = g_xh + (size_t)(m0 + lrow) * H_;
        }
        const size_t wr0 = ((size_t)(XP ? e * I_ : 0) + j0 + lrow) * (H_ / 8) + lq * 2;
        const int* gpr = (XP ? gp : sgp) + wr0;
        const int* upr = (XP ? up : sup) + wr0;
        const size_t sc0 = (size_t)(XP ? e * (H_ / GS_) * I_ : 0) + j0 + lrow;
        const float* gsp = (XP ? gsc : sgs) + sc0;
        const float* usp = (XP ? usc : sus) + sc0;
        const int bo = lrow * 128 + lq * 32;
        const __half* asrc0 = arow + lq * 16;

        // prologue: B(0) slot0; A(0) stage0; B(1) slot1
        cpa8(sb + G1_PG + tid * 8, gpr);
        cpa8(sb + G1_PU + tid * 8, upr);
        CP_COMMIT();
        cpa16(sb + G1_A + swoff(bo),      asrc0);
        cpa16(sb + G1_A + swoff(bo + 16), asrc0 + 8);
        CP_COMMIT();
        cpa8(sb + G1_PG + 4096 + tid * 8, gpr + 8);
        cpa8(sb + G1_PU + 4096 + tid * 8, upr + 8);
        CP_COMMIT();
        unsigned sg2 = pack_sc(gsp[0]), su2 = pack_sc(usp[0]);

        for (int c = 0; c < NC; c++) {
            const int st = c % 3;
            unsigned sg2N = sg2, su2N = su2;
            if (c + 1 < NC) {
                sg2N = pack_sc(gsp[(size_t)((c + 1) >> 1) * I_]);
                su2N = pack_sc(usp[(size_t)((c + 1) >> 1) * I_]);
            }
            if (c >= 2) {
                int ws = (c - 2) % 3, wp2 = ((c - 2) / 3) & 1;
                MBAR_WAIT(sb + 8 + 8 * ws, wp2);  // MMA(c-2) done -> stage free
            }
            if (c + 1 < NC) {
                unsigned adst = sb + G1_A + ((c + 1) % 3) * STG;
                const __half* asrc = asrc0 + (c + 1) * 64;
                cpa16(adst + swoff(bo),      asrc);
                cpa16(adst + swoff(bo + 16), asrc + 8);
            }
            CP_COMMIT();
            CP_WAIT(2);   // B(c) and A(c) landed (this thread's)
            int2 wg = *(const int2*)(smem + G1_PG + (c & 1) * 4096 + tid * 8);
            int2 wu = *(const int2*)(smem + G1_PU + (c & 1) * 4096 + tid * 8);
            char* Bg = smem + G1_BG + st * STG;
            char* Bu = smem + G1_BU + st * STG;
            st_sw(Bg, bo + 0,  dec8p((unsigned)wg.x, sg2));
            st_sw(Bg, bo + 16, dec8p((unsigned)wg.y, sg2));
            st_sw(Bu, bo + 0,  dec8p((unsigned)wu.x, su2));
            st_sw(Bu, bo + 16, dec8p((unsigned)wu.y, su2));
            if (c + 2 < NC) {
                cpa8(sb + G1_PG + (c & 1) * 4096 + tid * 8, gpr + (c + 2) * 8);
                cpa8(sb + G1_PU + (c & 1) * 4096 + tid * 8, upr + (c + 2) * 8);
            }
            CP_COMMIT();
            FENCE_ASYNC();
            MBAR_ARRIVE(sb + 32 + 8 * st);      // staging(c) done (this thread)
            sg2 = sg2N; su2 = su2N;
        }
        {
            const int ls = (NC - 1) % 3;
            MBAR_WAIT(sb + 8 + 8 * ls, (((NC - 1) - ls) / 3) & 1);
        }
    } else if (tid == 512) {
        // ------------------ MMA warp (elected thread) ------------------
        for (int c = 0; c < NC; c++) {
            const int st = c % 3;
            MBAR_WAIT(sb + 32 + 8 * st, (c / 3) & 1);   // all 512 staged
            unsigned long long ad = make_desc(sb + G1_A  + st * STG);
            unsigned long long gd = make_desc(sb + G1_BG + st * STG);
            unsigned long long ud = make_desc(sb + G1_BU + st * STG);
            #pragma unroll
            for (int ks = 0; ks < 4; ks++) {
                unsigned en = (c > 0 || ks > 0) ? 1u : 0u;
                mma_f16_ss(tb,       ad + ks * 2, gd + ks * 2, en);
                mma_f16_ss(tb + 128, ad + ks * 2, ud + ks * 2, en);
            }
            TC_COMMIT(sb + 8 + 8 * st);
        }
    }
    TC_FENCE_AFTER();

    // epilogue: warps 0-15 only; warp 16 just syncs
    if (wid < 16) {
        const int r = (wid & 3) * 32 + lid;
        const int cb = (wid >> 2) * 32;
        bool valid = XP ? (r < nrows) : true;
        __half* drow = XP ? (g_hbuf + ((size_t)e * C_ + r) * I_)
                          : (g_hsh  + (size_t)(m0 + r) * I_);
        unsigned gr[32], ur[32];
        TC_LD32(gr, tb + cb);
        TC_LD32(ur, tb + 128 + cb);
        TC_WAIT_LD();
        if (valid) {
            #pragma unroll
            for (int q = 0; q < 4; q++) {
                float v[8];
                #pragma unroll
                for (int t = 0; t < 8; t++) {
                    int j = q * 8 + t;
                    float gv = __uint_as_float(gr[j]);
                    float uv = __uint_as_float(ur[j]);
                    v[t] = gv / (1.f + __expf(-gv)) * uv;
                }
                uint4 o;
                o.x = h2u(__float22half2_rn(make_float2(v[0], v[1])));
                o.y = h2u(__float22half2_rn(make_float2(v[2], v[3])));
                o.z = h2u(__float22half2_rn(make_float2(v[4], v[5])));
                o.w = h2u(__float22half2_rn(make_float2(v[6], v[7])));
                *reinterpret_cast<uint4*>(drow + j0 + cb + q * 8) = o;
            }
        }
        TC_FENCE_BEFORE();
    }
    __syncthreads();
    if (tid == 0) {
        MBAR_INVAL(sb + 8);  MBAR_INVAL(sb + 16); MBAR_INVAL(sb + 24);
        MBAR_INVAL(sb + 32); MBAR_INVAL(sb + 40); MBAR_INVAL(sb + 48);
    }
    __syncthreads();
    if (wid == 0) { TC_RELINQ(); TC_DEALLOC(tb, 256); }
}

__global__ __launch_bounds__(544) void mma_gemm2(
    const int* __restrict__ dp, const float* __restrict__ dsc,
    const int* __restrict__ sdp, const float* __restrict__ sds,
    float* __restrict__ y) {
    constexpr int NC = I_ / 64;   // 24
    extern __shared__ char smem[];
    const int tid = threadIdx.x, wid = tid >> 5, lid = tid & 31;
    const int n0 = blockIdx.x * 128;
    const int by = blockIdx.y;
    const bool XP = by < E_;
    const int e  = XP ? by : 0;
    const int m0 = XP ? 0 : (by - E_) * 128;
    const int nrows = XP ? g_cnt[e] : 128;
    if (nrows == 0) return;

    unsigned sb = smem_u32(smem);
    if (wid == 0) TC_ALLOC(sb, 128);
    if (tid == 0) {
        MBAR_INIT(sb + 8, 1);  MBAR_INIT(sb + 16, 1); MBAR_INIT(sb + 24, 1);
        MBAR_INIT(sb + 32, 512); MBAR_INIT(sb + 40, 512); MBAR_INIT(sb + 48, 512);
    }
    __syncthreads();
    unsigned tb;
    asm("ld.shared.b32 %0, [%1];" : "=r"(tb) : "r"(sb));

    if (tid < 512) {
        const int lrow = tid >> 2, lq = tid & 3;
        const __half* arow = XP ? (g_hbuf + ((size_t)e * C_ + lrow) * I_)
                                : (g_hsh  + (size_t)(m0 + lrow) * I_);
        const int* dpr = (XP ? dp : sdp)
                       + ((size_t)(XP ? e * H_ : 0) + n0 + lrow) * (I_ / 8) + lq * 2;
        const float* dsp = (XP ? dsc : sds)
                         + (size_t)(XP ? e * (I_ / GS_) * H_ : 0) + n0 + lrow;
        const int bo = lrow * 128 + lq * 32;
        const __half* asrc0 = arow + lq * 16;

        // prologue: Bp(0); A(0)->stage0; Bp(1)
        cpa8(sb + G2_PB + tid * 8, dpr);
        CP_COMMIT();
        cpa16(sb + G2_A + swoff(bo),      asrc0);
        cpa16(sb + G2_A + swoff(bo + 16), asrc0 + 8);
        CP_COMMIT();
        cpa8(sb + G2_PB + 4096 + tid * 8, dpr + 8);
        CP_COMMIT();
        unsigned sd2 = pack_sc(dsp[0]);

        for (int c = 0; c < NC; c++) {
            const int st = c % 3;
            unsigned sd2N = sd2;
            if (c + 1 < NC) sd2N = pack_sc(dsp[(size_t)((c + 1) >> 1) * H_]);
            if (c >= 2) {
                int ws = (c - 2) % 3, wp2 = ((c - 2) / 3) & 1;
                MBAR_WAIT(sb + 8 + 8 * ws, wp2);
            }
            if (c + 1 < NC) {
                unsigned adst = sb + G2_A + ((c + 1) % 3) * STG;
                const __half* asrc = asrc0 + (c + 1) * 64;
                cpa16(adst + swoff(bo),      asrc);
                cpa16(adst + swoff(bo + 16), asrc + 8);
            }
            CP_COMMIT();
            CP_WAIT(2);
            int2 wd = *(const int2*)(smem + G2_PB + (c & 1) * 4096 + tid * 8);
            char* Bt = smem + G2_B + st * STG;
            st_sw(Bt, bo + 0,  dec8p((unsigned)wd.x, sd2));
            st_sw(Bt, bo + 16, dec8p((unsigned)wd.y, sd2));
            if (c + 2 < NC)
                cpa8(sb + G2_PB + (c & 1) * 4096 + tid * 8, dpr + (c + 2) * 8);
            CP_COMMIT();
            FENCE_ASYNC();
            MBAR_ARRIVE(sb + 32 + 8 * st);
            sd2 = sd2N;
        }
        {
            const int ls = (NC - 1) % 3;
            MBAR_WAIT(sb + 8 + 8 * ls, (((NC - 1) - ls) / 3) & 1);
        }
    } else if (tid == 512) {
        for (int c = 0; c < NC; c++) {
            const int st = c % 3;
            MBAR_WAIT(sb + 32 + 8 * st, (c / 3) & 1);
            unsigned long long ad = make_desc(sb + G2_A + st * STG);
            unsigned long long bd = make_desc(sb + G2_B + st * STG);
            #pragma unroll
            for (int ks = 0; ks < 4; ks++) {
                unsigned en = (c > 0 || ks > 0) ? 1u : 0u;
                mma_f16_ss(tb, ad + ks * 2, bd + ks * 2, en);
            }
            TC_COMMIT(sb + 8 + 8 * st);
        }
    }
    TC_FENCE_AFTER();

    if (wid < 16) {
        const int r = (wid & 3) * 32 + lid;
        const int cb = (wid >> 2) * 32;
        bool valid = XP ? (r < nrows) : true;
        int tok = 0; float wgt = 0.f;
        if (XP) { if (valid) { tok = g_slotTok[e * C_ + r]; wgt = g_slotW[e * C_ + r]; } }
        else    { tok = m0 + r; wgt = 1.f; }
        unsigned dr[32];
        TC_LD32(dr, tb + cb);
        TC_WAIT_LD();
        if (valid) {
            float* dst = y + (size_t)tok * H_ + n0 + cb;
            #pragma unroll
            for (int j = 0; j < 32; j += 4) {
                float v0 = wgt * __uint_as_float(dr[j]);
                float v1 = wgt * __uint_as_float(dr[j + 1]);
                float v2 = wgt * __uint_as_float(dr[j + 2]);
                float v3 = wgt * __uint_as_float(dr[j + 3]);
                asm volatile("red.global.add.v4.f32 [%0], {%1,%2,%3,%4};"
                    :: "l"(dst + j), "f"(v0), "f"(v1), "f"(v2), "f"(v3) : "memory");
            }
        }
        TC_FENCE_BEFORE();
    }
    __syncthreads();
    if (tid == 0) {
        MBAR_INVAL(sb + 8);  MBAR_INVAL(sb + 16); MBAR_INVAL(sb + 24);
        MBAR_INVAL(sb + 32); MBAR_INVAL(sb + 40); MBAR_INVAL(sb + 48);
    }
    __syncthreads();
    if (wid == 0) { TC_RELINQ(); TC_DEALLOC(tb, 128); }
}

#else  // !TC_OK
// ===========================================================================
// fallback: mma.sync (compiles for plain sm_103; never selected on GB300 —
// first 256 threads do the work, syncs stay block-wide)
// ===========================================================================
__device__ __forceinline__ void ldm_x4(unsigned r[4], unsigned a) {
    asm volatile("ldmatrix.sync.aligned.m8n8.x4.shared.b16 {%0,%1,%2,%3}, [%4];"
                 : "=r"(r[0]), "=r"(r[1]), "=r"(r[2]), "=r"(r[3]) : "r"(a));
}
__device__ __forceinline__ void ldm_x2(unsigned r[2], unsigned a) {
    asm volatile("ldmatrix.sync.aligned.m8n8.x2.shared.b16 {%0,%1}, [%2];"
                 : "=r"(r[0]), "=r"(r[1]) : "r"(a));
}
__device__ __forceinline__ void mma16816(float* d, const unsigned* a, const unsigned* b) {
    asm volatile("mma.sync.aligned.m16n8k16.row.col.f32.f16.f16.f32 "
        "{%0,%1,%2,%3}, {%4,%5,%6,%7}, {%8,%9}, {%0,%1,%2,%3};"
        : "+f"(d[0]), "+f"(d[1]), "+f"(d[2]), "+f"(d[3])
        : "r"(a[0]), "r"(a[1]), "r"(a[2]), "r"(a[3]), "r"(b[0]), "r"(b[1]));
}

__global__ __launch_bounds__(544) void mma_gemm1(
    const int* __restrict__ gp, const float* __restrict__ gsc,
    const int* __restrict__ up, const float* __restrict__ usc,
    const int* __restrict__ sgp, const float* __restrict__ sgs,
    const int* __restrict__ sup, const float* __restrict__ sus) {
    constexpr int NC = H_ / 64;
    extern __shared__ char smem[];
    const int tid = threadIdx.x;
    const bool act = tid < 256;
    const int t2 = tid & 255, wid = t2 >> 5, lane = t2 & 31;
    const int j0 = blockIdx.x * 128;
    const int by = blockIdx.y;
    const bool XP = by < E_;
    const int e  = XP ? by : 0;
    const int m0 = XP ? 0 : (by - E_) * 128;
    const int nrows = XP ? g_cnt[e] : 128;
    if (nrows == 0) return;

    unsigned sb = smem_u32(smem);
    const unsigned Ab = sb + G1_A, Bgb = sb + G1_BG, Bub = sb + G1_BU;
    const int lrow = t2 >> 1, lh = t2 & 1;
    const __half* arow;
    if (XP) {
        int tok = (lrow < nrows) ? g_slotTok[e * C_ + lrow] : 0;
        arow = g_xh + (size_t)tok * H_;
    } else {
        arow = g_xh + (size_t)(m0 + lrow) * H_;
    }
    const size_t wr0 = ((size_t)(XP ? e * I_ : 0) + j0 + lrow) * (H_ / 8) + lh * 4;
    const int* gpr = (XP ? gp : sgp) + wr0;
    const int* upr = (XP ? up : sup) + wr0;
    const size_t sc0 = (size_t)(XP ? e * (H_ / GS_) * I_ : 0) + j0 + lrow;
    const float* gsp = (XP ? gsc : sgs) + sc0;
    const float* usp = (XP ? usc : sus) + sc0;
    const int bo = lrow * 128 + lh * 64;
    const int wm = wid >> 2, wn = wid & 3;

    float ag[4][4][4], au[4][4][4];
    #pragma unroll
    for (int i = 0; i < 4; i++)
        #pragma unroll
        for (int j = 0; j < 4; j++)
            #pragma unroll
            for (int q = 0; q < 4; q++) { ag[i][j][q] = 0.f; au[i][j][q] = 0.f; }

    for (int c = 0; c < NC; c++) {
        int kk = c * 64;
        if (act) {
            stage_A_f16(smem + G1_A, arow, kk, bo, lh);
            stage_B4(smem + G1_BG, *(const int4*)(gpr + (kk >> 3)),
                     pack_sc(gsp[(size_t)(kk >> 7) * I_]), bo);
            stage_B4(smem + G1_BU, *(const int4*)(upr + (kk >> 3)),
                     pack_sc(usp[(size_t)(kk >> 7) * I_]), bo);
        }
        __syncthreads();
        if (act) {
            #pragma unroll
            for (int ks = 0; ks < 4; ks++) {
                unsigned af[4][4];
                #pragma unroll
                for (int mt = 0; mt < 4; mt++)
                    ldm_x4(af[mt], swadr(Ab, wm * 64 + mt * 16 + (lane & 15),
                                         ks * 32 + (lane >> 4) * 16));
                #pragma unroll
                for (int nt = 0; nt < 4; nt++) {
                    int brow = wn * 32 + nt * 8 + (lane & 7);
                    int bcol = ks * 32 + ((lane >> 3) & 1) * 16;
                    unsigned bg[2], bu[2];
                    ldm_x2(bg, swadr(Bgb, brow, bcol));
                    ldm_x2(bu, swadr(Bub, brow, bcol));
                    #pragma unroll
                    for (int mt = 0; mt < 4; mt++) {
                        mma16816(ag[mt][nt], af[mt], bg);
                        mma16816(au[mt][nt], af[mt], bu);
                    }
                }
            }
        }
        __syncthreads();
    }
    if (act) {
        const int g = lane >> 2, cq = lane & 3;
        #pragma unroll
        for (int mt = 0; mt < 4; mt++)
            #pragma unroll
            for (int nt = 0; nt < 4; nt++) {
                int nn = j0 + wn * 32 + nt * 8 + cq * 2;
                #pragma unroll
                for (int hrow = 0; hrow < 2; hrow++) {
                    int r = wm * 64 + mt * 16 + g + hrow * 8;
                    if (XP && r >= nrows) continue;
                    float g0 = ag[mt][nt][hrow * 2], g1 = ag[mt][nt][hrow * 2 + 1];
                    float u0 = au[mt][nt][hrow * 2], u1 = au[mt][nt][hrow * 2 + 1];
                    float v0 = g0 / (1.f + expf(-g0)) * u0;
                    float v1 = g1 / (1.f + expf(-g1)) * u1;
                    __half* dst = (XP ? g_hbuf + ((size_t)e * C_ + r) * I_
                                      : g_hsh + (size_t)(m0 + r) * I_) + nn;
                    *reinterpret_cast<__half2*>(dst) =
                        __float22half2_rn(make_float2(v0, v1));
                }
            }
    }
}

__global__ __launch_bounds__(544) void mma_gemm2(
    const int* __restrict__ dp, const float* __restrict__ dsc,
    const int* __restrict__ sdp, const float* __restrict__ sds,
    float* __restrict__ y) {
    constexpr int NC = I_ / 64;
    extern __shared__ char smem[];
    const int tid = threadIdx.x;
    const bool act = tid < 256;
    const int t2 = tid & 255, wid = t2 >> 5, lane = t2 & 31;
    const int n0 = blockIdx.x * 128;
    const int by = blockIdx.y;
    const bool XP = by < E_;
    const int e  = XP ? by : 0;
    const int m0 = XP ? 0 : (by - E_) * 128;
    const int nrows = XP ? g_cnt[e] : 128;
    if (nrows == 0) return;

    unsigned sb = smem_u32(smem);
    const unsigned Ab = sb + G2_A, Bb = sb + G2_B;
    const int lrow = t2 >> 1, lh = t2 & 1;
    const __half* arow = XP ? (g_hbuf + ((size_t)e * C_ + lrow) * I_)
                            : (g_hsh  + (size_t)(m0 + lrow) * I_);
    const int* dpr = (XP ? dp : sdp)
                   + ((size_t)(XP ? e * H_ : 0) + n0 + lrow) * (I_ / 8) + lh * 4;
    const float* dsp = (XP ? dsc : sds)
                     + (size_t)(XP ? e * (I_ / GS_) * H_ : 0) + n0 + lrow;
    const int bo = lrow * 128 + lh * 64;
    const int wm = wid >> 2, wn = wid & 3;

    float acc[4][4][4];
    #pragma unroll
    for (int i = 0; i < 4; i++)
        #pragma unroll
        for (int j = 0; j < 4; j++)
            #pragma unroll
            for (int q = 0; q < 4; q++) acc[i][j][q] = 0.f;

    for (int c = 0; c < NC; c++) {
        int kk = c * 64;
        if (act) {
            stage_A_f16(smem + G2_A, arow, kk, bo, lh);
            stage_B4(smem + G2_B, *(const int4*)(dpr + (kk >> 3)),
                     pack_sc(dsp[(size_t)(kk >> 7) * H_]), bo);
        }
        __syncthreads();
        if (act) {
            #pragma unroll
            for (int ks = 0; ks < 4; ks++) {
                unsigned af[4][4];
                #pragma unroll
                for (int mt = 0; mt < 4; mt++)
                    ldm_x4(af[mt], swadr(Ab, wm * 64 + mt * 16 + (lane & 15),
                                         ks * 32 + (lane >> 4) * 16));
                #pragma unroll
                for (int nt = 0; nt < 4; nt++) {
                    int brow = wn * 32 + nt * 8 + (lane & 7);
                    int bcol = ks * 32 + ((lane >> 3) & 1) * 16;
                    unsigned bf[2];
                    ldm_x2(bf, swadr(Bb, brow, bcol));
                    #pragma unroll
                    for (int mt = 0; mt < 4; mt++)
                        mma16816(acc[mt][nt], af[mt], bf);
                }
            }
        }
        __syncthreads();
    }
    if (act) {
        const int g = lane >> 2, cq = lane & 3;
        #pragma unroll
        for (int mt = 0; mt < 4; mt++)
            #pragma unroll
            for (int hrow = 0; hrow < 2; hrow++) {
                int r = wm * 64 + mt * 16 + g + hrow * 8;
                if (XP && r >= nrows) continue;
                int tok; float wgt;
                if (XP) { tok = g_slotTok[e * C_ + r]; wgt = g_slotW[e * C_ + r]; }
                else    { tok = m0 + r; wgt = 1.f; }
                #pragma unroll
                for (int nt = 0; nt < 4; nt++) {
                    int nn = n0 + wn * 32 + nt * 8 + cq * 2;
                    float* dst = y + (size_t)tok * H_ + nn;
                    atomicAdd(dst,     wgt * acc[mt][nt][hrow * 2]);
                    atomicAdd(dst + 1, wgt * acc[mt][nt][hrow * 2 + 1]);
                }
            }
    }
}
#endif  // TC_OK

// ---------------------------------------------------------------------------
// launch
// ---------------------------------------------------------------------------
extern "C" void kernel_launch(void* const* d_in, const int* in_sizes, int n_in,
                              void* d_out, int out_size) {
    const float* x   = (const float*)d_in[0];
    const float* gw  = (const float*)d_in[1];
    const float* gsc = (const float*)d_in[2];
    const float* usc = (const float*)d_in[3];
    const float* dsc = (const float*)d_in[4];
    const float* sgs = (const float*)d_in[5];
    const float* sus = (const float*)d_in[6];
    const float* sds = (const float*)d_in[7];
    const int*   gpk = (const int*)d_in[8];
    const int*   upk = (const int*)d_in[9];
    const int*   dpk = (const int*)d_in[10];
    const int*   sgp = (const int*)d_in[11];
    const int*   sup = (const int*)d_in[12];
    const int*   sdp = (const int*)d_in[13];
    float* y = (float*)d_out;

    cudaFuncSetAttribute(mma_gemm1, cudaFuncAttributeMaxDynamicSharedMemorySize, SM1);
    cudaFuncSetAttribute(mma_gemm2, cudaFuncAttributeMaxDynamicSharedMemorySize, SM2);

    routing_kernel<<<T_ / 4, 512>>>(x, gw);
    dispatch_kernel<<<2, 1024>>>();
    xcvt_zero_kernel<<<(T_ * H_ / 4) / 512, 512>>>((const float4*)x, (float4*)y);

    // stage 1: SwiGLU intermediates (experts y=0..63, shared tiles y=64..71)
    mma_gemm1<<<dim3(I_ / 128, E_ + T_ / 128), 544, SM1>>>(
        gpk, gsc, upk, usc, sgp, sgs, sup, sus);

    // stage 2: down-proj, all paths combine into zeroed y via red.v4
    mma_gemm2<<<dim3(H_ / 128, E_ + T_ / 128), 544, SM2>>>(
        dpk, dsc, sdp, sds, y);
}